// round 5
// baseline (speedup 1.0000x reference)
#include <cuda_runtime.h>
#include <cuda_bf16.h>
#include <math.h>
#include <stdint.h>

// Problem constants
constexpr int NB = 8;
constexpr int L  = 4096;
constexpr int S  = 4096;
constexpr int E  = 256;
constexpr int H  = 8;
constexpr int D  = 32;
constexpr int NL = NB * L;   // 32768
constexpr int NS = NB * S;   // 32768
constexpr float EPS = 1e-6f;
constexpr int KV_SPLIT = 8;

// ---------------- scratch (device globals; no allocation allowed) ----------------
__device__ float g_Qf[(size_t)NL * E];   // masked elu(Q)+1
__device__ float g_Kf[(size_t)NS * E];   // masked elu(K)+1
__device__ float g_Vm[(size_t)NS * E];   // masked V / S
__device__ float g_O [(size_t)NL * E];   // pre-merge output
__device__ float g_KV[(size_t)NB * H * D * D];
__device__ float g_Ksum[(size_t)NB * H * D];
__device__ float g_KVp[KV_SPLIT][(size_t)NB * H * D * D];
__device__ float g_Ksump[KV_SPLIT][(size_t)NB * H * D];
__device__ float g_qm[NL];
__device__ float g_km[NS];
__device__ int   g_mask_mode;            // 0=uint8, 1=int32, 2=float32

// ---------------- mask dtype detection + conversion ----------------
__global__ void detect_mask_kernel(const void* mask) {
    const unsigned char* b = (const unsigned char*)mask;
    int one_off1 = 0;
    int has3f = 0;
    for (int i = 0; i < 256; i++) {
        unsigned char c = b[i];
        if ((i & 3) == 1 && c == 1) one_off1++;
        if (c == 0x3F) has3f = 1;
    }
    g_mask_mode = (one_off1 > 0) ? 0 : (has3f ? 2 : 1);
}

__global__ void convert_mask_kernel(const void* __restrict__ m, float* __restrict__ out, int n) {
    int i = blockIdx.x * blockDim.x + threadIdx.x;
    if (i >= n) return;
    int mode = g_mask_mode;
    float v;
    if (mode == 0)      v = ((const unsigned char*)m)[i] ? 1.f : 0.f;
    else if (mode == 1) v = ((const int*)m)[i]           ? 1.f : 0.f;
    else                v = (((const float*)m)[i] != 0.f) ? 1.f : 0.f;
    out[i] = v;
}

// ---------------- tf32 helpers ----------------
__device__ __forceinline__ float cvt_tf32(float x) {
    uint32_t u;
    asm("cvt.rna.tf32.f32 %0, %1;" : "=r"(u) : "f"(x));
    return __uint_as_float(u);
}

__device__ __forceinline__ void mma_tf32(float (&d)[4], const uint32_t (&a)[4],
                                         uint32_t b0, uint32_t b1) {
    asm volatile(
        "mma.sync.aligned.m16n8k8.row.col.f32.tf32.tf32.f32 "
        "{%0,%1,%2,%3}, {%4,%5,%6,%7}, {%8,%9}, {%0,%1,%2,%3};"
        : "+f"(d[0]), "+f"(d[1]), "+f"(d[2]), "+f"(d[3])
        : "r"(a[0]), "r"(a[1]), "r"(a[2]), "r"(a[3]), "r"(b0), "r"(b1));
}

// ---------------- tf32 tensor-core GEMM: C = A @ W^T (+bias) with epilogue ----------------
// A: [M, E] row-major, W: [E, E] row-major (C[m,n] = sum_k A[m,k]*W[n,k])
// mode 0: plain    mode 1: (elu(x)+1) * rowmask    mode 2: x * rowmask * scale
//
// Quad-packed smem layout: fragment registers for each lane stored contiguously so
// MMA operand loads are single LDS.128 per 4 registers, conflict-free, linear addressing.
//   A elem [m][k] (m in [0,128), k in [0,16)):
//     Mt=m>>4, hi=(m>>3)&1, gm=m&7, kb=k>>3, kh=(k>>2)&1, tg=k&3
//     addr = kb*1024 + Mt*128 + (gm*4+tg)*4 + (hi + 2*kh)
//   B elem [n][k]: Pt=n>>4, jo=(n>>3)&1, gn=n&7  -> q = jo*2 + kh
//     addr = kb*1024 + Pt*128 + (gn*4+tg)*4 + (jo*2 + kh)
#define BM 128
#define BN 128
#define BK 16

__global__ __launch_bounds__(256, 2)
void gemm_tf32(const float* __restrict__ A,
               const float* __restrict__ W,
               const float* __restrict__ bias,
               float* __restrict__ C,
               const float* __restrict__ rowmask,
               float scale, int mode)
{
    __shared__ float As[BM * BK];   // 2048 floats
    __shared__ float Bs[BN * BK];   // 2048 floats

    const int tid  = threadIdx.x;
    const int m0   = blockIdx.y * BM;
    const int n0   = blockIdx.x * BN;
    const int wid  = tid >> 5;
    const int lane = tid & 31;
    const int wm   = (wid & 1) * 64;   // warp M offset (2 warps in M)
    const int wn   = (wid >> 1) * 32;  // warp N offset (4 warps in N)
    const int g    = lane >> 2;        // groupID (0..7)
    const int tg   = lane & 3;         // thread-in-group (0..3)
    const int Mtb  = (wid & 1) * 4;    // A quad-chunk base (Mt units of 16 rows)
    const int Pb   = (wid >> 1) * 2;   // B quad-chunk base (Pt units of 16 cols)

    // loader indices: thread loads float4 at rows lrow, lrow+64; cols lcol..lcol+3
    const int lrow = tid >> 2;         // 0..63
    const int lcol = (tid & 3) * 4;    // 0,4,8,12
    const int kb_  = lcol >> 3;        // 0..1
    const int kh_  = (lcol >> 2) & 1;  // 0..1

    float acc[4][4][4];
#pragma unroll
    for (int i = 0; i < 4; i++)
#pragma unroll
        for (int j = 0; j < 4; j++)
#pragma unroll
            for (int r = 0; r < 4; r++) acc[i][j][r] = 0.f;

    float4 pa[2], pb[2];

    // prefetch first k-tile
#pragma unroll
    for (int p = 0; p < 2; p++) {
        int r = lrow + 64 * p;
        pa[p] = *(const float4*)&A[(size_t)(m0 + r) * E + lcol];
        pb[p] = *(const float4*)&W[(size_t)(n0 + r) * E + lcol];
    }

    for (int k0 = 0; k0 < E; k0 += BK) {
        // ---- store staged tile into quad-packed smem (with tf32 rounding) ----
#pragma unroll
        for (int p = 0; p < 2; p++) {
            int r  = lrow + 64 * p;
            int Mt = r >> 4, hi = (r >> 3) & 1, gm = r & 7;
            int baseA = kb_ * 1024 + Mt * 128 + gm * 16 + (hi + 2 * kh_);
            As[baseA +  0] = cvt_tf32(pa[p].x);
            As[baseA +  4] = cvt_tf32(pa[p].y);
            As[baseA +  8] = cvt_tf32(pa[p].z);
            As[baseA + 12] = cvt_tf32(pa[p].w);
            int baseB = kb_ * 1024 + Mt * 128 + gm * 16 + (hi * 2 + kh_);  // q = jo*2+kh
            Bs[baseB +  0] = cvt_tf32(pb[p].x);
            Bs[baseB +  4] = cvt_tf32(pb[p].y);
            Bs[baseB +  8] = cvt_tf32(pb[p].z);
            Bs[baseB + 12] = cvt_tf32(pb[p].w);
        }
        __syncthreads();

        // ---- prefetch next k-tile while MMAs run ----
        if (k0 + BK < E) {
#pragma unroll
            for (int p = 0; p < 2; p++) {
                int r = lrow + 64 * p;
                pa[p] = *(const float4*)&A[(size_t)(m0 + r) * E + k0 + BK + lcol];
                pb[p] = *(const float4*)&W[(size_t)(n0 + r) * E + k0 + BK + lcol];
            }
        }

        // ---- 2 k8-steps of m16n8k8, quad LDS.128 fragment loads ----
#pragma unroll
        for (int kb = 0; kb < 2; kb++) {
            uint32_t a[4][4];
#pragma unroll
            for (int i = 0; i < 4; i++) {
                float4 q4 = *(const float4*)&As[kb * 1024 + (Mtb + i) * 128 + lane * 4];
                a[i][0] = __float_as_uint(q4.x); a[i][1] = __float_as_uint(q4.y);
                a[i][2] = __float_as_uint(q4.z); a[i][3] = __float_as_uint(q4.w);
            }
            uint32_t b[2][4];
#pragma unroll
            for (int jp = 0; jp < 2; jp++) {
                float4 q4 = *(const float4*)&Bs[kb * 1024 + (Pb + jp) * 128 + lane * 4];
                b[jp][0] = __float_as_uint(q4.x); b[jp][1] = __float_as_uint(q4.y);
                b[jp][2] = __float_as_uint(q4.z); b[jp][3] = __float_as_uint(q4.w);
            }
#pragma unroll
            for (int i = 0; i < 4; i++) {
#pragma unroll
                for (int jp = 0; jp < 2; jp++) {
                    mma_tf32(acc[i][2 * jp],     a[i], b[jp][0], b[jp][1]);
                    mma_tf32(acc[i][2 * jp + 1], a[i], b[jp][2], b[jp][3]);
                }
            }
        }
        __syncthreads();
    }

    // ---- epilogue ----
#pragma unroll
    for (int i = 0; i < 4; i++) {
        const int r0 = m0 + wm + i * 16 + g;
        const int r1 = r0 + 8;
        float rm0 = 0.f, rm1 = 0.f;
        if (mode != 0) { rm0 = rowmask[r0]; rm1 = rowmask[r1]; }
#pragma unroll
        for (int j = 0; j < 4; j++) {
            const int col = n0 + wn + j * 8 + 2 * tg;
            float b0 = 0.f, b1 = 0.f;
            if (bias) { b0 = bias[col]; b1 = bias[col + 1]; }
            float v0 = acc[i][j][0] + b0;
            float v1 = acc[i][j][1] + b1;
            float v2 = acc[i][j][2] + b0;
            float v3 = acc[i][j][3] + b1;
            if (mode == 1) {
                v0 = ((v0 > 0.f) ? (v0 + 1.f) : expf(v0)) * rm0;
                v1 = ((v1 > 0.f) ? (v1 + 1.f) : expf(v1)) * rm0;
                v2 = ((v2 > 0.f) ? (v2 + 1.f) : expf(v2)) * rm1;
                v3 = ((v3 > 0.f) ? (v3 + 1.f) : expf(v3)) * rm1;
            } else if (mode == 2) {
                v0 *= rm0 * scale; v1 *= rm0 * scale;
                v2 *= rm1 * scale; v3 *= rm1 * scale;
            }
            *(float2*)&C[(size_t)r0 * E + col] = make_float2(v0, v1);
            *(float2*)&C[(size_t)r1 * E + col] = make_float2(v2, v3);
        }
    }
}

// ---------------- KV aggregation (s-split): partial KV[n,h,d,v], Ksum[n,h,d] ----------------
__global__ __launch_bounds__(256)
void kv_agg_kernel(const float* __restrict__ Kf, const float* __restrict__ Vm)
{
    const int n = blockIdx.x >> 3;
    const int h = blockIdx.x & 7;
    const int split = blockIdx.y;
    const int sbeg = split * (S / KV_SPLIT);
    const int send = sbeg + (S / KV_SPLIT);

    __shared__ float sK[64][40];
    __shared__ float sV[64][40];
    __shared__ float red[4][64][16];

    const int tid = threadIdx.x;
    const int g = tid >> 6;             // s-split group 0..3
    const int t = tid & 63;
    const int db = (t >> 3) << 2;       // d base
    const int vb = (t & 7) << 2;        // v base

    const int lr = tid >> 3;            // 0..31
    const int lc = (tid & 7) << 2;      // 0..28

    float acc[4][4];
#pragma unroll
    for (int i = 0; i < 4; i++)
#pragma unroll
        for (int j = 0; j < 4; j++) acc[i][j] = 0.f;
    float ksum = 0.f;

    const size_t base = (size_t)n * S * E + (size_t)h * D;

    for (int s0 = sbeg; s0 < send; s0 += 64) {
#pragma unroll
        for (int p = 0; p < 2; p++) {
            int r = lr + p * 32;
            size_t off = base + (size_t)(s0 + r) * E + lc;
            *(float4*)&sK[r][lc] = *(const float4*)&Kf[off];
            *(float4*)&sV[r][lc] = *(const float4*)&Vm[off];
        }
        __syncthreads();

        for (int ss = g; ss < 64; ss += 4) {
            float4 k4 = *(const float4*)&sK[ss][db];
            float4 v4 = *(const float4*)&sV[ss][vb];
            acc[0][0] += k4.x * v4.x; acc[0][1] += k4.x * v4.y; acc[0][2] += k4.x * v4.z; acc[0][3] += k4.x * v4.w;
            acc[1][0] += k4.y * v4.x; acc[1][1] += k4.y * v4.y; acc[1][2] += k4.y * v4.z; acc[1][3] += k4.y * v4.w;
            acc[2][0] += k4.z * v4.x; acc[2][1] += k4.z * v4.y; acc[2][2] += k4.z * v4.z; acc[2][3] += k4.z * v4.w;
            acc[3][0] += k4.w * v4.x; acc[3][1] += k4.w * v4.y; acc[3][2] += k4.w * v4.z; acc[3][3] += k4.w * v4.w;
        }
        if (g == 0 && t < 32) {
#pragma unroll
            for (int ss = 0; ss < 64; ss++) ksum += sK[ss][t];
        }
        __syncthreads();
    }

    // cross-group reduction
#pragma unroll
    for (int jd = 0; jd < 4; jd++)
#pragma unroll
        for (int jv = 0; jv < 4; jv++) red[g][t][jd * 4 + jv] = acc[jd][jv];
    __syncthreads();

    const size_t kvbase = (size_t)((n * H + h) * D) * D;
#pragma unroll
    for (int q = 0; q < 4; q++) {
        int o = tid * 4 + q;
        int d = o >> 5, v = o & 31;
        int tt = ((d >> 2) << 3) | (v >> 2);
        int jj = ((d & 3) << 2) | (v & 3);
        float val = red[0][tt][jj] + red[1][tt][jj] + red[2][tt][jj] + red[3][tt][jj];
        g_KVp[split][kvbase + (size_t)d * D + v] = val;
    }
    if (g == 0 && t < 32) g_Ksump[split][(size_t)(n * H + h) * D + t] = ksum;
}

// ---------------- KV partial reduction ----------------
__global__ void kv_reduce_kernel() {
    const int NKV = NB * H * D * D;     // 65536
    const int NKS = NB * H * D;         // 2048
    int i = blockIdx.x * blockDim.x + threadIdx.x;
    if (i < NKV) {
        float s = 0.f;
#pragma unroll
        for (int p = 0; p < KV_SPLIT; p++) s += g_KVp[p][i];
        g_KV[i] = s;
    } else if (i < NKV + NKS) {
        int j = i - NKV;
        float s = 0.f;
#pragma unroll
        for (int p = 0; p < KV_SPLIT; p++) s += g_Ksump[p][j];
        g_Ksum[j] = s;
    }
}

// ---------------- attention apply: O = (Qf @ KV) * Z * S ----------------
__global__ __launch_bounds__(256)
void attn_kernel(const float* __restrict__ Qf, float* __restrict__ O)
{
    const int bid  = blockIdx.x;
    const int n    = bid >> 12;
    const int h    = (bid >> 9) & 7;
    const int lgrp = bid & 511;

    __shared__ float sKV[32][32];
    __shared__ float sKs[32];

    const int tid = threadIdx.x;
    const float* kvp = g_KV + (size_t)((n * H + h) * D) * D;
    ((float4*)sKV)[tid] = ((const float4*)kvp)[tid];
    if (tid < 32) sKs[tid] = g_Ksum[(size_t)(n * H + h) * D + tid];
    __syncthreads();

    const int w = tid >> 5, lane = tid & 31;
    const int l = (lgrp << 3) | w;
    const size_t ro = ((size_t)n * L + l) * E + (size_t)h * D;

    float qf = Qf[ro + lane];
    float z = qf * sKs[lane];
#pragma unroll
    for (int o = 16; o; o >>= 1) z += __shfl_xor_sync(0xffffffffu, z, o);
    float zinv = (float)S / (z + EPS);

    float acc = 0.f;
#pragma unroll
    for (int d = 0; d < 32; d++)
        acc += __shfl_sync(0xffffffffu, qf, d) * sKV[d][lane];

    O[ro + lane] = acc * zinv;
}

// ---------------- launch ----------------
extern "C" void kernel_launch(void* const* d_in, const int* in_sizes, int n_in,
                              void* d_out, int out_size)
{
    const float* q   = (const float*)d_in[0];
    const float* k   = (const float*)d_in[1];
    const float* v   = (const float*)d_in[2];
    const void*  qmask = d_in[3];
    const void*  kmask = d_in[4];
    const float* Wq  = (const float*)d_in[5];
    const float* bq  = (const float*)d_in[6];
    const float* Wk  = (const float*)d_in[7];
    const float* bk  = (const float*)d_in[8];
    const float* Wv  = (const float*)d_in[9];
    const float* bv  = (const float*)d_in[10];
    const float* Wm  = (const float*)d_in[11];
    float* out = (float*)d_out;

    float* g_qm_p; cudaGetSymbolAddress((void**)&g_qm_p, g_qm);
    float* g_km_p; cudaGetSymbolAddress((void**)&g_km_p, g_km);
    float* g_Qf_p; cudaGetSymbolAddress((void**)&g_Qf_p, g_Qf);
    float* g_Kf_p; cudaGetSymbolAddress((void**)&g_Kf_p, g_Kf);
    float* g_Vm_p; cudaGetSymbolAddress((void**)&g_Vm_p, g_Vm);
    float* g_O_p;  cudaGetSymbolAddress((void**)&g_O_p,  g_O);

    // 1) mask dtype detect + convert
    detect_mask_kernel<<<1, 1>>>(qmask);
    convert_mask_kernel<<<(NL + 255) / 256, 256>>>(qmask, g_qm_p, NL);
    convert_mask_kernel<<<(NS + 255) / 256, 256>>>(kmask, g_km_p, NS);

    // 2) fused QKV projections (tf32 tensor cores)
    dim3 ggrid(E / BN, NL / BM);
    gemm_tf32<<<ggrid, 256>>>(q, Wq, bq, g_Qf_p, g_qm_p, 1.0f, 1);            // Qf = (elu+1)*qm
    gemm_tf32<<<ggrid, 256>>>(k, Wk, bk, g_Kf_p, g_km_p, 1.0f, 1);            // Kf = (elu+1)*km
    gemm_tf32<<<ggrid, 256>>>(v, Wv, bv, g_Vm_p, g_km_p, 1.0f / (float)S, 2); // Vm = V*km/S

    // 3) KV aggregation (s-split) + reduction
    dim3 kvgrid(NB * H, KV_SPLIT);
    kv_agg_kernel<<<kvgrid, 256>>>(g_Kf_p, g_Vm_p);
    kv_reduce_kernel<<<(NB * H * D * D + NB * H * D + 255) / 256, 256>>>();

    // 4) attention apply
    attn_kernel<<<NB * H * (L / 8), 256>>>(g_Qf_p, g_O_p);

    // 5) merge projection (no bias)
    gemm_tf32<<<ggrid, 256>>>(g_O_p, Wm, nullptr, out, nullptr, 1.0f, 0);
}

// round 6
// speedup vs baseline: 1.0096x; 1.0096x over previous
#include <cuda_runtime.h>
#include <cuda_bf16.h>
#include <math.h>
#include <stdint.h>

// Problem constants
constexpr int NB = 8;
constexpr int L  = 4096;
constexpr int S  = 4096;
constexpr int E  = 256;
constexpr int H  = 8;
constexpr int D  = 32;
constexpr int NL = NB * L;   // 32768
constexpr int NS = NB * S;   // 32768
constexpr float EPS = 1e-6f;
constexpr int KV_SPLIT = 8;

// ---------------- scratch (device globals; no allocation allowed) ----------------
__device__ float g_Qf[(size_t)NL * E];   // masked elu(Q)+1
__device__ float g_Kf[(size_t)NS * E];   // masked elu(K)+1
__device__ float g_Vm[(size_t)NS * E];   // masked V / S
__device__ float g_O [(size_t)NL * E];   // pre-merge output
__device__ float g_KV[(size_t)NB * H * D * D];
__device__ float g_Ksum[(size_t)NB * H * D];
__device__ float g_KVp[KV_SPLIT][(size_t)NB * H * D * D];
__device__ float g_Ksump[KV_SPLIT][(size_t)NB * H * D];
__device__ float g_qm[NL];
__device__ float g_km[NS];
__device__ int   g_mask_mode;            // 0=uint8, 1=int32, 2=float32

// ---------------- mask dtype detection + conversion ----------------
__global__ void detect_mask_kernel(const void* mask) {
    const unsigned char* b = (const unsigned char*)mask;
    int one_off1 = 0;
    int has3f = 0;
    for (int i = 0; i < 256; i++) {
        unsigned char c = b[i];
        if ((i & 3) == 1 && c == 1) one_off1++;
        if (c == 0x3F) has3f = 1;
    }
    g_mask_mode = (one_off1 > 0) ? 0 : (has3f ? 2 : 1);
}

__global__ void convert_mask_kernel(const void* __restrict__ m, float* __restrict__ out, int n) {
    int i = blockIdx.x * blockDim.x + threadIdx.x;
    if (i >= n) return;
    int mode = g_mask_mode;
    float v;
    if (mode == 0)      v = ((const unsigned char*)m)[i] ? 1.f : 0.f;
    else if (mode == 1) v = ((const int*)m)[i]           ? 1.f : 0.f;
    else                v = (((const float*)m)[i] != 0.f) ? 1.f : 0.f;
    out[i] = v;
}

// ---------------- tf32 helpers ----------------
__device__ __forceinline__ float cvt_tf32(float x) {
    uint32_t u;
    asm("cvt.rna.tf32.f32 %0, %1;" : "=r"(u) : "f"(x));
    return __uint_as_float(u);
}

__device__ __forceinline__ void mma_tf32(float (&d)[4], const uint32_t (&a)[4],
                                         uint32_t b0, uint32_t b1) {
    asm volatile(
        "mma.sync.aligned.m16n8k8.row.col.f32.tf32.tf32.f32 "
        "{%0,%1,%2,%3}, {%4,%5,%6,%7}, {%8,%9}, {%0,%1,%2,%3};"
        : "+f"(d[0]), "+f"(d[1]), "+f"(d[2]), "+f"(d[3])
        : "r"(a[0]), "r"(a[1]), "r"(a[2]), "r"(a[3]), "r"(b0), "r"(b1));
}

// ---------------- tf32 tensor-core GEMM: C = A @ W^T (+bias) with epilogue ----------------
// A: [M, E] row-major, W: [E, E] row-major (C[m,n] = sum_k A[m,k]*W[n,k])
// mode 0: plain    mode 1: (elu(x)+1) * rowmask    mode 2: x * rowmask * scale
//
// Quad-packed smem layout: fragment registers for each lane stored contiguously so
// MMA operand loads are single LDS.128 per 4 registers, conflict-free, linear addressing.
//   A elem [m][k] (m in [0,128), k in [0,16)):
//     Mt=m>>4, hi=(m>>3)&1, gm=m&7, kb=k>>3, kh=(k>>2)&1, tg=k&3
//     addr = kb*1024 + Mt*128 + (gm*4+tg)*4 + (hi + 2*kh)
//   B elem [n][k]: Pt=n>>4, jo=(n>>3)&1, gn=n&7  -> q = jo*2 + kh
//     addr = kb*1024 + Pt*128 + (gn*4+tg)*4 + (jo*2 + kh)
#define BM 128
#define BN 128
#define BK 16

__global__ __launch_bounds__(256, 2)
void gemm_tf32(const float* __restrict__ A,
               const float* __restrict__ W,
               const float* __restrict__ bias,
               float* __restrict__ C,
               const float* __restrict__ rowmask,
               float scale, int mode)
{
    __shared__ float As[BM * BK];   // 2048 floats
    __shared__ float Bs[BN * BK];   // 2048 floats

    const int tid  = threadIdx.x;
    const int m0   = blockIdx.y * BM;
    const int n0   = blockIdx.x * BN;
    const int wid  = tid >> 5;
    const int lane = tid & 31;
    const int wm   = (wid & 1) * 64;   // warp M offset (2 warps in M)
    const int wn   = (wid >> 1) * 32;  // warp N offset (4 warps in N)
    const int g    = lane >> 2;        // groupID (0..7)
    const int tg   = lane & 3;         // thread-in-group (0..3)
    const int Mtb  = (wid & 1) * 4;    // A quad-chunk base (Mt units of 16 rows)
    const int Pb   = (wid >> 1) * 2;   // B quad-chunk base (Pt units of 16 cols)

    // loader indices: thread loads float4 at rows lrow, lrow+64; cols lcol..lcol+3
    const int lrow = tid >> 2;         // 0..63
    const int lcol = (tid & 3) * 4;    // 0,4,8,12
    const int kb_  = lcol >> 3;        // 0..1
    const int kh_  = (lcol >> 2) & 1;  // 0..1

    float acc[4][4][4];
#pragma unroll
    for (int i = 0; i < 4; i++)
#pragma unroll
        for (int j = 0; j < 4; j++)
#pragma unroll
            for (int r = 0; r < 4; r++) acc[i][j][r] = 0.f;

    float4 pa[2], pb[2];

    // prefetch first k-tile
#pragma unroll
    for (int p = 0; p < 2; p++) {
        int r = lrow + 64 * p;
        pa[p] = *(const float4*)&A[(size_t)(m0 + r) * E + lcol];
        pb[p] = *(const float4*)&W[(size_t)(n0 + r) * E + lcol];
    }

    for (int k0 = 0; k0 < E; k0 += BK) {
        // ---- store staged tile into quad-packed smem (with tf32 rounding) ----
#pragma unroll
        for (int p = 0; p < 2; p++) {
            int r  = lrow + 64 * p;
            int Mt = r >> 4, hi = (r >> 3) & 1, gm = r & 7;
            int baseA = kb_ * 1024 + Mt * 128 + gm * 16 + (hi + 2 * kh_);
            As[baseA +  0] = cvt_tf32(pa[p].x);
            As[baseA +  4] = cvt_tf32(pa[p].y);
            As[baseA +  8] = cvt_tf32(pa[p].z);
            As[baseA + 12] = cvt_tf32(pa[p].w);
            int baseB = kb_ * 1024 + Mt * 128 + gm * 16 + (hi * 2 + kh_);  // q = jo*2+kh
            Bs[baseB +  0] = cvt_tf32(pb[p].x);
            Bs[baseB +  4] = cvt_tf32(pb[p].y);
            Bs[baseB +  8] = cvt_tf32(pb[p].z);
            Bs[baseB + 12] = cvt_tf32(pb[p].w);
        }
        __syncthreads();

        // ---- prefetch next k-tile while MMAs run ----
        if (k0 + BK < E) {
#pragma unroll
            for (int p = 0; p < 2; p++) {
                int r = lrow + 64 * p;
                pa[p] = *(const float4*)&A[(size_t)(m0 + r) * E + k0 + BK + lcol];
                pb[p] = *(const float4*)&W[(size_t)(n0 + r) * E + k0 + BK + lcol];
            }
        }

        // ---- 2 k8-steps of m16n8k8, quad LDS.128 fragment loads ----
#pragma unroll
        for (int kb = 0; kb < 2; kb++) {
            uint32_t a[4][4];
#pragma unroll
            for (int i = 0; i < 4; i++) {
                float4 q4 = *(const float4*)&As[kb * 1024 + (Mtb + i) * 128 + lane * 4];
                a[i][0] = __float_as_uint(q4.x); a[i][1] = __float_as_uint(q4.y);
                a[i][2] = __float_as_uint(q4.z); a[i][3] = __float_as_uint(q4.w);
            }
            uint32_t b[2][4];
#pragma unroll
            for (int jp = 0; jp < 2; jp++) {
                float4 q4 = *(const float4*)&Bs[kb * 1024 + (Pb + jp) * 128 + lane * 4];
                b[jp][0] = __float_as_uint(q4.x); b[jp][1] = __float_as_uint(q4.y);
                b[jp][2] = __float_as_uint(q4.z); b[jp][3] = __float_as_uint(q4.w);
            }
#pragma unroll
            for (int i = 0; i < 4; i++) {
#pragma unroll
                for (int jp = 0; jp < 2; jp++) {
                    mma_tf32(acc[i][2 * jp],     a[i], b[jp][0], b[jp][1]);
                    mma_tf32(acc[i][2 * jp + 1], a[i], b[jp][2], b[jp][3]);
                }
            }
        }
        __syncthreads();
    }

    // ---- epilogue ----
#pragma unroll
    for (int i = 0; i < 4; i++) {
        const int r0 = m0 + wm + i * 16 + g;
        const int r1 = r0 + 8;
        float rm0 = 0.f, rm1 = 0.f;
        if (mode != 0) { rm0 = rowmask[r0]; rm1 = rowmask[r1]; }
#pragma unroll
        for (int j = 0; j < 4; j++) {
            const int col = n0 + wn + j * 8 + 2 * tg;
            float b0 = 0.f, b1 = 0.f;
            if (bias) { b0 = bias[col]; b1 = bias[col + 1]; }
            float v0 = acc[i][j][0] + b0;
            float v1 = acc[i][j][1] + b1;
            float v2 = acc[i][j][2] + b0;
            float v3 = acc[i][j][3] + b1;
            if (mode == 1) {
                v0 = ((v0 > 0.f) ? (v0 + 1.f) : expf(v0)) * rm0;
                v1 = ((v1 > 0.f) ? (v1 + 1.f) : expf(v1)) * rm0;
                v2 = ((v2 > 0.f) ? (v2 + 1.f) : expf(v2)) * rm1;
                v3 = ((v3 > 0.f) ? (v3 + 1.f) : expf(v3)) * rm1;
            } else if (mode == 2) {
                v0 *= rm0 * scale; v1 *= rm0 * scale;
                v2 *= rm1 * scale; v3 *= rm1 * scale;
            }
            *(float2*)&C[(size_t)r0 * E + col] = make_float2(v0, v1);
            *(float2*)&C[(size_t)r1 * E + col] = make_float2(v2, v3);
        }
    }
}

// ---------------- KV aggregation (s-split): partial KV[n,h,d,v], Ksum[n,h,d] ----------------
__global__ __launch_bounds__(256)
void kv_agg_kernel(const float* __restrict__ Kf, const float* __restrict__ Vm)
{
    const int n = blockIdx.x >> 3;
    const int h = blockIdx.x & 7;
    const int split = blockIdx.y;
    const int sbeg = split * (S / KV_SPLIT);
    const int send = sbeg + (S / KV_SPLIT);

    __shared__ float sK[64][40];
    __shared__ float sV[64][40];
    __shared__ float red[4][64][16];

    const int tid = threadIdx.x;
    const int g = tid >> 6;             // s-split group 0..3
    const int t = tid & 63;
    const int db = (t >> 3) << 2;       // d base
    const int vb = (t & 7) << 2;        // v base

    const int lr = tid >> 3;            // 0..31
    const int lc = (tid & 7) << 2;      // 0..28

    float acc[4][4];
#pragma unroll
    for (int i = 0; i < 4; i++)
#pragma unroll
        for (int j = 0; j < 4; j++) acc[i][j] = 0.f;
    float ksum = 0.f;

    const size_t base = (size_t)n * S * E + (size_t)h * D;

    for (int s0 = sbeg; s0 < send; s0 += 64) {
#pragma unroll
        for (int p = 0; p < 2; p++) {
            int r = lr + p * 32;
            size_t off = base + (size_t)(s0 + r) * E + lc;
            *(float4*)&sK[r][lc] = *(const float4*)&Kf[off];
            *(float4*)&sV[r][lc] = *(const float4*)&Vm[off];
        }
        __syncthreads();

        for (int ss = g; ss < 64; ss += 4) {
            float4 k4 = *(const float4*)&sK[ss][db];
            float4 v4 = *(const float4*)&sV[ss][vb];
            acc[0][0] += k4.x * v4.x; acc[0][1] += k4.x * v4.y; acc[0][2] += k4.x * v4.z; acc[0][3] += k4.x * v4.w;
            acc[1][0] += k4.y * v4.x; acc[1][1] += k4.y * v4.y; acc[1][2] += k4.y * v4.z; acc[1][3] += k4.y * v4.w;
            acc[2][0] += k4.z * v4.x; acc[2][1] += k4.z * v4.y; acc[2][2] += k4.z * v4.z; acc[2][3] += k4.z * v4.w;
            acc[3][0] += k4.w * v4.x; acc[3][1] += k4.w * v4.y; acc[3][2] += k4.w * v4.z; acc[3][3] += k4.w * v4.w;
        }
        if (g == 0 && t < 32) {
#pragma unroll
            for (int ss = 0; ss < 64; ss++) ksum += sK[ss][t];
        }
        __syncthreads();
    }

    // cross-group reduction
#pragma unroll
    for (int jd = 0; jd < 4; jd++)
#pragma unroll
        for (int jv = 0; jv < 4; jv++) red[g][t][jd * 4 + jv] = acc[jd][jv];
    __syncthreads();

    const size_t kvbase = (size_t)((n * H + h) * D) * D;
#pragma unroll
    for (int q = 0; q < 4; q++) {
        int o = tid * 4 + q;
        int d = o >> 5, v = o & 31;
        int tt = ((d >> 2) << 3) | (v >> 2);
        int jj = ((d & 3) << 2) | (v & 3);
        float val = red[0][tt][jj] + red[1][tt][jj] + red[2][tt][jj] + red[3][tt][jj];
        g_KVp[split][kvbase + (size_t)d * D + v] = val;
    }
    if (g == 0 && t < 32) g_Ksump[split][(size_t)(n * H + h) * D + t] = ksum;
}

// ---------------- KV partial reduction ----------------
__global__ void kv_reduce_kernel() {
    const int NKV = NB * H * D * D;     // 65536
    const int NKS = NB * H * D;         // 2048
    int i = blockIdx.x * blockDim.x + threadIdx.x;
    if (i < NKV) {
        float s = 0.f;
#pragma unroll
        for (int p = 0; p < KV_SPLIT; p++) s += g_KVp[p][i];
        g_KV[i] = s;
    } else if (i < NKV + NKS) {
        int j = i - NKV;
        float s = 0.f;
#pragma unroll
        for (int p = 0; p < KV_SPLIT; p++) s += g_Ksump[p][j];
        g_Ksum[j] = s;
    }
}

// ---------------- attention apply: O = (Qf @ KV) * Z * S ----------------
__global__ __launch_bounds__(256)
void attn_kernel(const float* __restrict__ Qf, float* __restrict__ O)
{
    const int bid  = blockIdx.x;
    const int n    = bid >> 12;
    const int h    = (bid >> 9) & 7;
    const int lgrp = bid & 511;

    __shared__ float sKV[32][32];
    __shared__ float sKs[32];

    const int tid = threadIdx.x;
    const float* kvp = g_KV + (size_t)((n * H + h) * D) * D;
    ((float4*)sKV)[tid] = ((const float4*)kvp)[tid];
    if (tid < 32) sKs[tid] = g_Ksum[(size_t)(n * H + h) * D + tid];
    __syncthreads();

    const int w = tid >> 5, lane = tid & 31;
    const int l = (lgrp << 3) | w;
    const size_t ro = ((size_t)n * L + l) * E + (size_t)h * D;

    float qf = Qf[ro + lane];
    float z = qf * sKs[lane];
#pragma unroll
    for (int o = 16; o; o >>= 1) z += __shfl_xor_sync(0xffffffffu, z, o);
    float zinv = (float)S / (z + EPS);

    float acc = 0.f;
#pragma unroll
    for (int d = 0; d < 32; d++)
        acc += __shfl_sync(0xffffffffu, qf, d) * sKV[d][lane];

    O[ro + lane] = acc * zinv;
}

// ---------------- launch ----------------
extern "C" void kernel_launch(void* const* d_in, const int* in_sizes, int n_in,
                              void* d_out, int out_size)
{
    const float* q   = (const float*)d_in[0];
    const float* k   = (const float*)d_in[1];
    const float* v   = (const float*)d_in[2];
    const void*  qmask = d_in[3];
    const void*  kmask = d_in[4];
    const float* Wq  = (const float*)d_in[5];
    const float* bq  = (const float*)d_in[6];
    const float* Wk  = (const float*)d_in[7];
    const float* bk  = (const float*)d_in[8];
    const float* Wv  = (const float*)d_in[9];
    const float* bv  = (const float*)d_in[10];
    const float* Wm  = (const float*)d_in[11];
    float* out = (float*)d_out;

    float* g_qm_p; cudaGetSymbolAddress((void**)&g_qm_p, g_qm);
    float* g_km_p; cudaGetSymbolAddress((void**)&g_km_p, g_km);
    float* g_Qf_p; cudaGetSymbolAddress((void**)&g_Qf_p, g_Qf);
    float* g_Kf_p; cudaGetSymbolAddress((void**)&g_Kf_p, g_Kf);
    float* g_Vm_p; cudaGetSymbolAddress((void**)&g_Vm_p, g_Vm);
    float* g_O_p;  cudaGetSymbolAddress((void**)&g_O_p,  g_O);

    // 1) mask dtype detect + convert
    detect_mask_kernel<<<1, 1>>>(qmask);
    convert_mask_kernel<<<(NL + 255) / 256, 256>>>(qmask, g_qm_p, NL);
    convert_mask_kernel<<<(NS + 255) / 256, 256>>>(kmask, g_km_p, NS);

    // 2) fused QKV projections (tf32 tensor cores)
    dim3 ggrid(E / BN, NL / BM);
    gemm_tf32<<<ggrid, 256>>>(q, Wq, bq, g_Qf_p, g_qm_p, 1.0f, 1);            // Qf = (elu+1)*qm
    gemm_tf32<<<ggrid, 256>>>(k, Wk, bk, g_Kf_p, g_km_p, 1.0f, 1);            // Kf = (elu+1)*km
    gemm_tf32<<<ggrid, 256>>>(v, Wv, bv, g_Vm_p, g_km_p, 1.0f / (float)S, 2); // Vm = V*km/S

    // 3) KV aggregation (s-split) + reduction
    dim3 kvgrid(NB * H, KV_SPLIT);
    kv_agg_kernel<<<kvgrid, 256>>>(g_Kf_p, g_Vm_p);
    kv_reduce_kernel<<<(NB * H * D * D + NB * H * D + 255) / 256, 256>>>();

    // 4) attention apply
    attn_kernel<<<NB * H * (L / 8), 256>>>(g_Qf_p, g_O_p);

    // 5) merge projection (no bias)
    gemm_tf32<<<ggrid, 256>>>(g_O_p, Wm, nullptr, out, nullptr, 1.0f, 0);
}

// round 7
// speedup vs baseline: 1.0162x; 1.0065x over previous
#include <cuda_runtime.h>
#include <cuda_bf16.h>
#include <math.h>
#include <stdint.h>

// Problem constants
constexpr int NB = 8;
constexpr int L  = 4096;
constexpr int S  = 4096;
constexpr int E  = 256;
constexpr int H  = 8;
constexpr int D  = 32;
constexpr int NL = NB * L;   // 32768
constexpr int NS = NB * S;   // 32768
constexpr float EPS = 1e-6f;
constexpr int KV_SPLIT = 8;

// ---------------- scratch (device globals; no allocation allowed) ----------------
__device__ float g_Qf[(size_t)NL * E];   // masked elu(Q)+1
__device__ float g_Kf[(size_t)NS * E];   // masked elu(K)+1
__device__ float g_Vm[(size_t)NS * E];   // masked V / S
__device__ float g_O [(size_t)NL * E];   // pre-merge output
__device__ float g_KV[(size_t)NB * H * D * D];
__device__ float g_Ksum[(size_t)NB * H * D];
__device__ float g_KVp[KV_SPLIT][(size_t)NB * H * D * D];
__device__ float g_Ksump[KV_SPLIT][(size_t)NB * H * D];
__device__ float g_qm[NL];
__device__ float g_km[NS];
__device__ int   g_mask_mode;            // 0=uint8, 1=int32, 2=float32

// ---------------- mask dtype detection + conversion ----------------
__global__ void detect_mask_kernel(const void* mask) {
    const unsigned char* b = (const unsigned char*)mask;
    int one_off1 = 0;
    int has3f = 0;
    for (int i = 0; i < 256; i++) {
        unsigned char c = b[i];
        if ((i & 3) == 1 && c == 1) one_off1++;
        if (c == 0x3F) has3f = 1;
    }
    g_mask_mode = (one_off1 > 0) ? 0 : (has3f ? 2 : 1);
}

__global__ void convert_mask_kernel(const void* __restrict__ m, float* __restrict__ out, int n) {
    int i = blockIdx.x * blockDim.x + threadIdx.x;
    if (i >= n) return;
    int mode = g_mask_mode;
    float v;
    if (mode == 0)      v = ((const unsigned char*)m)[i] ? 1.f : 0.f;
    else if (mode == 1) v = ((const int*)m)[i]           ? 1.f : 0.f;
    else                v = (((const float*)m)[i] != 0.f) ? 1.f : 0.f;
    out[i] = v;
}

// ---------------- tf32 helpers ----------------
__device__ __forceinline__ float cvt_tf32(float x) {
    uint32_t u;
    asm("cvt.rna.tf32.f32 %0, %1;" : "=r"(u) : "f"(x));
    return __uint_as_float(u);
}

__device__ __forceinline__ void mma_tf32(float (&d)[4], const uint32_t (&a)[4],
                                         uint32_t b0, uint32_t b1) {
    asm volatile(
        "mma.sync.aligned.m16n8k8.row.col.f32.tf32.tf32.f32 "
        "{%0,%1,%2,%3}, {%4,%5,%6,%7}, {%8,%9}, {%0,%1,%2,%3};"
        : "+f"(d[0]), "+f"(d[1]), "+f"(d[2]), "+f"(d[3])
        : "r"(a[0]), "r"(a[1]), "r"(a[2]), "r"(a[3]), "r"(b0), "r"(b1));
}

// ---------------- tf32 tensor-core GEMM: C = A @ W^T (+bias) with epilogue ----------------
// A: [M, E] row-major, W: [E, E] row-major (C[m,n] = sum_k A[m,k]*W[n,k])
// mode 0: plain    mode 1: (elu(x)+1) * rowmask    mode 2: x * rowmask * scale
//
// Quad-packed smem layout: fragment registers for each lane stored contiguously so
// MMA operand loads are single LDS.128 per 4 registers, conflict-free, linear addressing.
//   A elem [m][k] (m in [0,128), k in [0,16)):
//     Mt=m>>4, hi=(m>>3)&1, gm=m&7, kb=k>>3, kh=(k>>2)&1, tg=k&3
//     addr = kb*1024 + Mt*128 + (gm*4+tg)*4 + (hi + 2*kh)
//   B elem [n][k]: Pt=n>>4, jo=(n>>3)&1, gn=n&7  -> q = jo*2 + kh
//     addr = kb*1024 + Pt*128 + (gn*4+tg)*4 + (jo*2 + kh)
#define BM 128
#define BN 128
#define BK 16

__global__ __launch_bounds__(256, 2)
void gemm_tf32(const float* __restrict__ A,
               const float* __restrict__ W,
               const float* __restrict__ bias,
               float* __restrict__ C,
               const float* __restrict__ rowmask,
               float scale, int mode)
{
    __shared__ float As[BM * BK];   // 2048 floats
    __shared__ float Bs[BN * BK];   // 2048 floats

    const int tid  = threadIdx.x;
    const int m0   = blockIdx.y * BM;
    const int n0   = blockIdx.x * BN;
    const int wid  = tid >> 5;
    const int lane = tid & 31;
    const int wm   = (wid & 1) * 64;   // warp M offset (2 warps in M)
    const int wn   = (wid >> 1) * 32;  // warp N offset (4 warps in N)
    const int g    = lane >> 2;        // groupID (0..7)
    const int tg   = lane & 3;         // thread-in-group (0..3)
    const int Mtb  = (wid & 1) * 4;    // A quad-chunk base (Mt units of 16 rows)
    const int Pb   = (wid >> 1) * 2;   // B quad-chunk base (Pt units of 16 cols)

    // loader indices: thread loads float4 at rows lrow, lrow+64; cols lcol..lcol+3
    const int lrow = tid >> 2;         // 0..63
    const int lcol = (tid & 3) * 4;    // 0,4,8,12
    const int kb_  = lcol >> 3;        // 0..1
    const int kh_  = (lcol >> 2) & 1;  // 0..1

    float acc[4][4][4];
#pragma unroll
    for (int i = 0; i < 4; i++)
#pragma unroll
        for (int j = 0; j < 4; j++)
#pragma unroll
            for (int r = 0; r < 4; r++) acc[i][j][r] = 0.f;

    float4 pa[2], pb[2];

    // prefetch first k-tile
#pragma unroll
    for (int p = 0; p < 2; p++) {
        int r = lrow + 64 * p;
        pa[p] = *(const float4*)&A[(size_t)(m0 + r) * E + lcol];
        pb[p] = *(const float4*)&W[(size_t)(n0 + r) * E + lcol];
    }

    for (int k0 = 0; k0 < E; k0 += BK) {
        // ---- store staged tile into quad-packed smem (with tf32 rounding) ----
#pragma unroll
        for (int p = 0; p < 2; p++) {
            int r  = lrow + 64 * p;
            int Mt = r >> 4, hi = (r >> 3) & 1, gm = r & 7;
            int baseA = kb_ * 1024 + Mt * 128 + gm * 16 + (hi + 2 * kh_);
            As[baseA +  0] = cvt_tf32(pa[p].x);
            As[baseA +  4] = cvt_tf32(pa[p].y);
            As[baseA +  8] = cvt_tf32(pa[p].z);
            As[baseA + 12] = cvt_tf32(pa[p].w);
            int baseB = kb_ * 1024 + Mt * 128 + gm * 16 + (hi * 2 + kh_);  // q = jo*2+kh
            Bs[baseB +  0] = cvt_tf32(pb[p].x);
            Bs[baseB +  4] = cvt_tf32(pb[p].y);
            Bs[baseB +  8] = cvt_tf32(pb[p].z);
            Bs[baseB + 12] = cvt_tf32(pb[p].w);
        }
        __syncthreads();

        // ---- prefetch next k-tile while MMAs run ----
        if (k0 + BK < E) {
#pragma unroll
            for (int p = 0; p < 2; p++) {
                int r = lrow + 64 * p;
                pa[p] = *(const float4*)&A[(size_t)(m0 + r) * E + k0 + BK + lcol];
                pb[p] = *(const float4*)&W[(size_t)(n0 + r) * E + k0 + BK + lcol];
            }
        }

        // ---- 2 k8-steps of m16n8k8, quad LDS.128 fragment loads ----
#pragma unroll
        for (int kb = 0; kb < 2; kb++) {
            uint32_t a[4][4];
#pragma unroll
            for (int i = 0; i < 4; i++) {
                float4 q4 = *(const float4*)&As[kb * 1024 + (Mtb + i) * 128 + lane * 4];
                a[i][0] = __float_as_uint(q4.x); a[i][1] = __float_as_uint(q4.y);
                a[i][2] = __float_as_uint(q4.z); a[i][3] = __float_as_uint(q4.w);
            }
            uint32_t b[2][4];
#pragma unroll
            for (int jp = 0; jp < 2; jp++) {
                float4 q4 = *(const float4*)&Bs[kb * 1024 + (Pb + jp) * 128 + lane * 4];
                b[jp][0] = __float_as_uint(q4.x); b[jp][1] = __float_as_uint(q4.y);
                b[jp][2] = __float_as_uint(q4.z); b[jp][3] = __float_as_uint(q4.w);
            }
#pragma unroll
            for (int i = 0; i < 4; i++) {
#pragma unroll
                for (int jp = 0; jp < 2; jp++) {
                    mma_tf32(acc[i][2 * jp],     a[i], b[jp][0], b[jp][1]);
                    mma_tf32(acc[i][2 * jp + 1], a[i], b[jp][2], b[jp][3]);
                }
            }
        }
        __syncthreads();
    }

    // ---- epilogue ----
#pragma unroll
    for (int i = 0; i < 4; i++) {
        const int r0 = m0 + wm + i * 16 + g;
        const int r1 = r0 + 8;
        float rm0 = 0.f, rm1 = 0.f;
        if (mode != 0) { rm0 = rowmask[r0]; rm1 = rowmask[r1]; }
#pragma unroll
        for (int j = 0; j < 4; j++) {
            const int col = n0 + wn + j * 8 + 2 * tg;
            float b0 = 0.f, b1 = 0.f;
            if (bias) { b0 = bias[col]; b1 = bias[col + 1]; }
            float v0 = acc[i][j][0] + b0;
            float v1 = acc[i][j][1] + b1;
            float v2 = acc[i][j][2] + b0;
            float v3 = acc[i][j][3] + b1;
            if (mode == 1) {
                v0 = ((v0 > 0.f) ? (v0 + 1.f) : expf(v0)) * rm0;
                v1 = ((v1 > 0.f) ? (v1 + 1.f) : expf(v1)) * rm0;
                v2 = ((v2 > 0.f) ? (v2 + 1.f) : expf(v2)) * rm1;
                v3 = ((v3 > 0.f) ? (v3 + 1.f) : expf(v3)) * rm1;
            } else if (mode == 2) {
                v0 *= rm0 * scale; v1 *= rm0 * scale;
                v2 *= rm1 * scale; v3 *= rm1 * scale;
            }
            *(float2*)&C[(size_t)r0 * E + col] = make_float2(v0, v1);
            *(float2*)&C[(size_t)r1 * E + col] = make_float2(v2, v3);
        }
    }
}

// ---------------- KV aggregation (s-split): partial KV[n,h,d,v], Ksum[n,h,d] ----------------
__global__ __launch_bounds__(256)
void kv_agg_kernel(const float* __restrict__ Kf, const float* __restrict__ Vm)
{
    const int n = blockIdx.x >> 3;
    const int h = blockIdx.x & 7;
    const int split = blockIdx.y;
    const int sbeg = split * (S / KV_SPLIT);
    const int send = sbeg + (S / KV_SPLIT);

    __shared__ float sK[64][40];
    __shared__ float sV[64][40];
    __shared__ float red[4][64][16];

    const int tid = threadIdx.x;
    const int g = tid >> 6;             // s-split group 0..3
    const int t = tid & 63;
    const int db = (t >> 3) << 2;       // d base
    const int vb = (t & 7) << 2;        // v base

    const int lr = tid >> 3;            // 0..31
    const int lc = (tid & 7) << 2;      // 0..28

    float acc[4][4];
#pragma unroll
    for (int i = 0; i < 4; i++)
#pragma unroll
        for (int j = 0; j < 4; j++) acc[i][j] = 0.f;
    float ksum = 0.f;

    const size_t base = (size_t)n * S * E + (size_t)h * D;

    for (int s0 = sbeg; s0 < send; s0 += 64) {
#pragma unroll
        for (int p = 0; p < 2; p++) {
            int r = lr + p * 32;
            size_t off = base + (size_t)(s0 + r) * E + lc;
            *(float4*)&sK[r][lc] = *(const float4*)&Kf[off];
            *(float4*)&sV[r][lc] = *(const float4*)&Vm[off];
        }
        __syncthreads();

        for (int ss = g; ss < 64; ss += 4) {
            float4 k4 = *(const float4*)&sK[ss][db];
            float4 v4 = *(const float4*)&sV[ss][vb];
            acc[0][0] += k4.x * v4.x; acc[0][1] += k4.x * v4.y; acc[0][2] += k4.x * v4.z; acc[0][3] += k4.x * v4.w;
            acc[1][0] += k4.y * v4.x; acc[1][1] += k4.y * v4.y; acc[1][2] += k4.y * v4.z; acc[1][3] += k4.y * v4.w;
            acc[2][0] += k4.z * v4.x; acc[2][1] += k4.z * v4.y; acc[2][2] += k4.z * v4.z; acc[2][3] += k4.z * v4.w;
            acc[3][0] += k4.w * v4.x; acc[3][1] += k4.w * v4.y; acc[3][2] += k4.w * v4.z; acc[3][3] += k4.w * v4.w;
        }
        if (g == 0 && t < 32) {
#pragma unroll
            for (int ss = 0; ss < 64; ss++) ksum += sK[ss][t];
        }
        __syncthreads();
    }

    // cross-group reduction
#pragma unroll
    for (int jd = 0; jd < 4; jd++)
#pragma unroll
        for (int jv = 0; jv < 4; jv++) red[g][t][jd * 4 + jv] = acc[jd][jv];
    __syncthreads();

    const size_t kvbase = (size_t)((n * H + h) * D) * D;
#pragma unroll
    for (int q = 0; q < 4; q++) {
        int o = tid * 4 + q;
        int d = o >> 5, v = o & 31;
        int tt = ((d >> 2) << 3) | (v >> 2);
        int jj = ((d & 3) << 2) | (v & 3);
        float val = red[0][tt][jj] + red[1][tt][jj] + red[2][tt][jj] + red[3][tt][jj];
        g_KVp[split][kvbase + (size_t)d * D + v] = val;
    }
    if (g == 0 && t < 32) g_Ksump[split][(size_t)(n * H + h) * D + t] = ksum;
}

// ---------------- KV partial reduction ----------------
__global__ void kv_reduce_kernel() {
    const int NKV = NB * H * D * D;     // 65536
    const int NKS = NB * H * D;         // 2048
    int i = blockIdx.x * blockDim.x + threadIdx.x;
    if (i < NKV) {
        float s = 0.f;
#pragma unroll
        for (int p = 0; p < KV_SPLIT; p++) s += g_KVp[p][i];
        g_KV[i] = s;
    } else if (i < NKV + NKS) {
        int j = i - NKV;
        float s = 0.f;
#pragma unroll
        for (int p = 0; p < KV_SPLIT; p++) s += g_Ksump[p][j];
        g_Ksum[j] = s;
    }
}

// ---------------- attention apply: O = (Qf @ KV) * Z * S ----------------
__global__ __launch_bounds__(256)
void attn_kernel(const float* __restrict__ Qf, float* __restrict__ O)
{
    const int bid  = blockIdx.x;
    const int n    = bid >> 12;
    const int h    = (bid >> 9) & 7;
    const int lgrp = bid & 511;

    __shared__ float sKV[32][32];
    __shared__ float sKs[32];

    const int tid = threadIdx.x;
    const float* kvp = g_KV + (size_t)((n * H + h) * D) * D;
    ((float4*)sKV)[tid] = ((const float4*)kvp)[tid];
    if (tid < 32) sKs[tid] = g_Ksum[(size_t)(n * H + h) * D + tid];
    __syncthreads();

    const int w = tid >> 5, lane = tid & 31;
    const int l = (lgrp << 3) | w;
    const size_t ro = ((size_t)n * L + l) * E + (size_t)h * D;

    float qf = Qf[ro + lane];
    float z = qf * sKs[lane];
#pragma unroll
    for (int o = 16; o; o >>= 1) z += __shfl_xor_sync(0xffffffffu, z, o);
    float zinv = (float)S / (z + EPS);

    float acc = 0.f;
#pragma unroll
    for (int d = 0; d < 32; d++)
        acc += __shfl_sync(0xffffffffu, qf, d) * sKV[d][lane];

    O[ro + lane] = acc * zinv;
}

// ---------------- launch ----------------
extern "C" void kernel_launch(void* const* d_in, const int* in_sizes, int n_in,
                              void* d_out, int out_size)
{
    const float* q   = (const float*)d_in[0];
    const float* k   = (const float*)d_in[1];
    const float* v   = (const float*)d_in[2];
    const void*  qmask = d_in[3];
    const void*  kmask = d_in[4];
    const float* Wq  = (const float*)d_in[5];
    const float* bq  = (const float*)d_in[6];
    const float* Wk  = (const float*)d_in[7];
    const float* bk  = (const float*)d_in[8];
    const float* Wv  = (const float*)d_in[9];
    const float* bv  = (const float*)d_in[10];
    const float* Wm  = (const float*)d_in[11];
    float* out = (float*)d_out;

    float* g_qm_p; cudaGetSymbolAddress((void**)&g_qm_p, g_qm);
    float* g_km_p; cudaGetSymbolAddress((void**)&g_km_p, g_km);
    float* g_Qf_p; cudaGetSymbolAddress((void**)&g_Qf_p, g_Qf);
    float* g_Kf_p; cudaGetSymbolAddress((void**)&g_Kf_p, g_Kf);
    float* g_Vm_p; cudaGetSymbolAddress((void**)&g_Vm_p, g_Vm);
    float* g_O_p;  cudaGetSymbolAddress((void**)&g_O_p,  g_O);

    // 1) mask dtype detect + convert
    detect_mask_kernel<<<1, 1>>>(qmask);
    convert_mask_kernel<<<(NL + 255) / 256, 256>>>(qmask, g_qm_p, NL);
    convert_mask_kernel<<<(NS + 255) / 256, 256>>>(kmask, g_km_p, NS);

    // 2) fused QKV projections (tf32 tensor cores)
    dim3 ggrid(E / BN, NL / BM);
    gemm_tf32<<<ggrid, 256>>>(q, Wq, bq, g_Qf_p, g_qm_p, 1.0f, 1);            // Qf = (elu+1)*qm
    gemm_tf32<<<ggrid, 256>>>(k, Wk, bk, g_Kf_p, g_km_p, 1.0f, 1);            // Kf = (elu+1)*km
    gemm_tf32<<<ggrid, 256>>>(v, Wv, bv, g_Vm_p, g_km_p, 1.0f / (float)S, 2); // Vm = V*km/S

    // 3) KV aggregation (s-split) + reduction
    dim3 kvgrid(NB * H, KV_SPLIT);
    kv_agg_kernel<<<kvgrid, 256>>>(g_Kf_p, g_Vm_p);
    kv_reduce_kernel<<<(NB * H * D * D + NB * H * D + 255) / 256, 256>>>();

    // 4) attention apply
    attn_kernel<<<NB * H * (L / 8), 256>>>(g_Qf_p, g_O_p);

    // 5) merge projection (no bias)
    gemm_tf32<<<ggrid, 256>>>(g_O_p, Wm, nullptr, out, nullptr, 1.0f, 0);
}

// round 11
// speedup vs baseline: 1.6594x; 1.6330x over previous
#include <cuda_runtime.h>
#include <cuda_fp16.h>
#include <math.h>
#include <stdint.h>

// Problem constants
constexpr int NB = 8;
constexpr int L  = 4096;
constexpr int S  = 4096;
constexpr int E  = 256;
constexpr int H  = 8;
constexpr int D  = 32;
constexpr int NL = NB * L;   // 32768
constexpr int NS = NB * S;   // 32768
constexpr float EPS = 1e-6f;
constexpr int KV_SPLIT = 8;

// ---------------- scratch (device globals; no allocation allowed) ----------------
__device__ float g_Qf[(size_t)NL * E];
__device__ float g_Kf[(size_t)NS * E];
__device__ float g_Vm[(size_t)NS * E];
__device__ float g_O [(size_t)NL * E];
__device__ float g_KV[(size_t)NB * H * D * D];
__device__ float g_Ksum[(size_t)NB * H * D];
__device__ float g_KVp[KV_SPLIT][(size_t)NB * H * D * D];
__device__ float g_Ksump[KV_SPLIT][(size_t)NB * H * D];
__device__ float g_qm[NL];
__device__ float g_km[NS];
__device__ int   g_mask_mode;

// ---------------- mask dtype detection + conversion ----------------
__global__ void detect_mask_kernel(const void* mask) {
    const unsigned char* b = (const unsigned char*)mask;
    int one_off1 = 0;
    int has3f = 0;
    for (int i = 0; i < 256; i++) {
        unsigned char c = b[i];
        if ((i & 3) == 1 && c == 1) one_off1++;
        if (c == 0x3F) has3f = 1;
    }
    g_mask_mode = (one_off1 > 0) ? 0 : (has3f ? 2 : 1);
}

__global__ void convert_mask_kernel(const void* __restrict__ m, float* __restrict__ out, int n) {
    int i = blockIdx.x * blockDim.x + threadIdx.x;
    if (i >= n) return;
    int mode = g_mask_mode;
    float v;
    if (mode == 0)      v = ((const unsigned char*)m)[i] ? 1.f : 0.f;
    else if (mode == 1) v = ((const int*)m)[i]           ? 1.f : 0.f;
    else                v = (((const float*)m)[i] != 0.f) ? 1.f : 0.f;
    out[i] = v;
}

// ---------------- fp16 MMA helpers ----------------
__device__ __forceinline__ uint32_t smem_u32(const void* p) {
    uint32_t r;
    asm("{ .reg .u64 t; cvta.to.shared.u64 t, %1; cvt.u32.u64 %0, t; }" : "=r"(r) : "l"(p));
    return r;
}

__device__ __forceinline__ uint32_t pack_h2(float x, float y) {
    __half2 h = __floats2half2_rn(x, y);
    return *(uint32_t*)&h;
}

__device__ __forceinline__ void ldmx4(uint32_t (&r)[4], uint32_t addr) {
    asm volatile("ldmatrix.sync.aligned.m8n8.x4.shared.b16 {%0,%1,%2,%3}, [%4];"
                 : "=r"(r[0]), "=r"(r[1]), "=r"(r[2]), "=r"(r[3]) : "r"(addr));
}

__device__ __forceinline__ void mma_f16(float (&d)[4], const uint32_t (&a)[4],
                                        uint32_t b0, uint32_t b1) {
    asm volatile(
        "mma.sync.aligned.m16n8k16.row.col.f32.f16.f16.f32 "
        "{%0,%1,%2,%3}, {%4,%5,%6,%7}, {%8,%9}, {%0,%1,%2,%3};"
        : "+f"(d[0]), "+f"(d[1]), "+f"(d[2]), "+f"(d[3])
        : "r"(a[0]), "r"(a[1]), "r"(a[2]), "r"(a[3]), "r"(b0), "r"(b1));
}

// ---------------- fp16 tensor-core GEMM: C = A @ W^T (+bias) with epilogue ----------------
// A: [M, E] row-major fp32, W: [E, E] row-major fp32 (C[m,n] = sum_k A[m,k]*W[n,k])
// mode 0: plain    mode 1: (elu(x)+1) * rowmask    mode 2: x * rowmask * scale
//
// Block tile 128x128, BK=32 (fp16 in smem).  SMEM layout per matrix: 128 rows x 64B
// (32 halves).  16B chunk c16 of row r stored at  r*64 + (c16 ^ ((r>>1)&3))*16  —
// conflict-free for both the fill STS.128 and every ldmatrix 8-address phase.
#define BM 128
#define BN 128
#define BK 32

__global__ __launch_bounds__(256, 2)
void gemm_f16(const float* __restrict__ A,
              const float* __restrict__ W,
              const float* __restrict__ bias,
              float* __restrict__ C,
              const float* __restrict__ rowmask,
              float scale, int mode)
{
    __shared__ __align__(16) unsigned char smA[BM * 64];  // 8KB
    __shared__ __align__(16) unsigned char smB[BN * 64];  // 8KB

    const int tid  = threadIdx.x;
    const int wid  = tid >> 5;
    const int lane = tid & 31;
    const int m0   = blockIdx.y * BM;
    const int n0   = blockIdx.x * BN;
    const int wm   = (wid & 1) * 64;   // warp M offset (2 warps in M)
    const int wn   = (wid >> 1) * 32;  // warp N offset (4 warps in N)
    const int g    = lane >> 2;
    const int tg   = lane & 3;

    const uint32_t sA = smem_u32(smA);
    const uint32_t sB = smem_u32(smB);

    // ---- fill indices (constant across k-tiles) ----
    // chunk idx = p*256 + tid ; r = idx>>2 ; c16 = idx&3
    int   fr[2], fc[2];
    uint32_t foff[2];
#pragma unroll
    for (int p = 0; p < 2; p++) {
        int idx = p * 256 + tid;
        fr[p] = idx >> 2;
        fc[p] = idx & 3;
        foff[p] = (uint32_t)(fr[p] * 64 + ((fc[p] ^ ((fr[p] >> 1) & 3)) << 4));
    }

    // ---- ldmatrix addresses (constant across k-tiles; 8 for A, 4 for B per s) ----
    uint32_t adA[4][2], adB[2][2];
#pragma unroll
    for (int i = 0; i < 4; i++) {
        int r = wm + i * 16 + ((lane >> 3) & 1) * 8 + (lane & 7);
#pragma unroll
        for (int s = 0; s < 2; s++) {
            int kc = 2 * s + (lane >> 4);
            adA[i][s] = sA + (uint32_t)(r * 64 + ((kc ^ ((r >> 1) & 3)) << 4));
        }
    }
#pragma unroll
    for (int jp = 0; jp < 2; jp++) {
        int r = wn + (2 * jp + ((lane >> 3) >> 1)) * 8 + (lane & 7);
#pragma unroll
        for (int s = 0; s < 2; s++) {
            int kc = 2 * s + ((lane >> 3) & 1);
            adB[jp][s] = sB + (uint32_t)(r * 64 + ((kc ^ ((r >> 1) & 3)) << 4));
        }
    }

    float acc[4][4][4];
#pragma unroll
    for (int i = 0; i < 4; i++)
#pragma unroll
        for (int j = 0; j < 4; j++)
#pragma unroll
            for (int r = 0; r < 4; r++) acc[i][j][r] = 0.f;

    // ---- prologue: load+convert tile 0 into staged regs ----
    uint4 stA[2], stB[2];
#pragma unroll
    for (int p = 0; p < 2; p++) {
        const float* pa = &A[(size_t)(m0 + fr[p]) * E + fc[p] * 8];
        float4 f0 = *(const float4*)pa;
        float4 f1 = *(const float4*)(pa + 4);
        stA[p] = make_uint4(pack_h2(f0.x, f0.y), pack_h2(f0.z, f0.w),
                            pack_h2(f1.x, f1.y), pack_h2(f1.z, f1.w));
        const float* pb = &W[(size_t)(n0 + fr[p]) * E + fc[p] * 8];
        float4 g0 = *(const float4*)pb;
        float4 g1 = *(const float4*)(pb + 4);
        stB[p] = make_uint4(pack_h2(g0.x, g0.y), pack_h2(g0.z, g0.w),
                            pack_h2(g1.x, g1.y), pack_h2(g1.z, g1.w));
    }

    for (int k0 = 0; k0 < E; k0 += BK) {
        // ---- commit staged tile to smem ----
#pragma unroll
        for (int p = 0; p < 2; p++) {
            *(uint4*)(smA + foff[p]) = stA[p];
            *(uint4*)(smB + foff[p]) = stB[p];
        }
        __syncthreads();

        // ---- prefetch next tile (load + convert) while MMAs run ----
        if (k0 + BK < E) {
#pragma unroll
            for (int p = 0; p < 2; p++) {
                const float* pa = &A[(size_t)(m0 + fr[p]) * E + k0 + BK + fc[p] * 8];
                float4 f0 = *(const float4*)pa;
                float4 f1 = *(const float4*)(pa + 4);
                stA[p] = make_uint4(pack_h2(f0.x, f0.y), pack_h2(f0.z, f0.w),
                                    pack_h2(f1.x, f1.y), pack_h2(f1.z, f1.w));
                const float* pb = &W[(size_t)(n0 + fr[p]) * E + k0 + BK + fc[p] * 8];
                float4 g0 = *(const float4*)pb;
                float4 g1 = *(const float4*)(pb + 4);
                stB[p] = make_uint4(pack_h2(g0.x, g0.y), pack_h2(g0.z, g0.w),
                                    pack_h2(g1.x, g1.y), pack_h2(g1.z, g1.w));
            }
        }

        // ---- 2 k16-steps: 6 ldmatrix.x4 + 16 MMA per step per warp ----
#pragma unroll
        for (int s = 0; s < 2; s++) {
            uint32_t a[4][4];
#pragma unroll
            for (int i = 0; i < 4; i++) ldmx4(a[i], adA[i][s]);
            uint32_t bb[2][4];
#pragma unroll
            for (int jp = 0; jp < 2; jp++) ldmx4(bb[jp], adB[jp][s]);
#pragma unroll
            for (int i = 0; i < 4; i++) {
#pragma unroll
                for (int j = 0; j < 4; j++) {
                    const int jp = j >> 1, hi = j & 1;
                    mma_f16(acc[i][j], a[i], bb[jp][hi * 2], bb[jp][hi * 2 + 1]);
                }
            }
        }
        __syncthreads();
    }

    // ---- epilogue (same mapping as R4) ----
#pragma unroll
    for (int i = 0; i < 4; i++) {
        const int r0 = m0 + wm + i * 16 + g;
        const int r1 = r0 + 8;
        float rm0 = 0.f, rm1 = 0.f;
        if (mode != 0) { rm0 = rowmask[r0]; rm1 = rowmask[r1]; }
#pragma unroll
        for (int j = 0; j < 4; j++) {
            const int col = n0 + wn + j * 8 + 2 * tg;
            float b0 = 0.f, b1 = 0.f;
            if (bias) { b0 = bias[col]; b1 = bias[col + 1]; }
            float v0 = acc[i][j][0] + b0;
            float v1 = acc[i][j][1] + b1;
            float v2 = acc[i][j][2] + b0;
            float v3 = acc[i][j][3] + b1;
            if (mode == 1) {
                v0 = ((v0 > 0.f) ? (v0 + 1.f) : expf(v0)) * rm0;
                v1 = ((v1 > 0.f) ? (v1 + 1.f) : expf(v1)) * rm0;
                v2 = ((v2 > 0.f) ? (v2 + 1.f) : expf(v2)) * rm1;
                v3 = ((v3 > 0.f) ? (v3 + 1.f) : expf(v3)) * rm1;
            } else if (mode == 2) {
                v0 *= rm0 * scale; v1 *= rm0 * scale;
                v2 *= rm1 * scale; v3 *= rm1 * scale;
            }
            *(float2*)&C[(size_t)r0 * E + col] = make_float2(v0, v1);
            *(float2*)&C[(size_t)r1 * E + col] = make_float2(v2, v3);
        }
    }
}

// ---------------- KV aggregation (s-split): partial KV[n,h,d,v], Ksum[n,h,d] ----------------
__global__ __launch_bounds__(256)
void kv_agg_kernel(const float* __restrict__ Kf, const float* __restrict__ Vm)
{
    const int n = blockIdx.x >> 3;
    const int h = blockIdx.x & 7;
    const int split = blockIdx.y;
    const int sbeg = split * (S / KV_SPLIT);
    const int send = sbeg + (S / KV_SPLIT);

    __shared__ float sK[64][40];
    __shared__ float sV[64][40];
    __shared__ float red[4][64][16];

    const int tid = threadIdx.x;
    const int g = tid >> 6;
    const int t = tid & 63;
    const int db = (t >> 3) << 2;
    const int vb = (t & 7) << 2;

    const int lr = tid >> 3;
    const int lc = (tid & 7) << 2;

    float acc[4][4];
#pragma unroll
    for (int i = 0; i < 4; i++)
#pragma unroll
        for (int j = 0; j < 4; j++) acc[i][j] = 0.f;
    float ksum = 0.f;

    const size_t base = (size_t)n * S * E + (size_t)h * D;

    for (int s0 = sbeg; s0 < send; s0 += 64) {
#pragma unroll
        for (int p = 0; p < 2; p++) {
            int r = lr + p * 32;
            size_t off = base + (size_t)(s0 + r) * E + lc;
            *(float4*)&sK[r][lc] = *(const float4*)&Kf[off];
            *(float4*)&sV[r][lc] = *(const float4*)&Vm[off];
        }
        __syncthreads();

        for (int ss = g; ss < 64; ss += 4) {
            float4 k4 = *(const float4*)&sK[ss][db];
            float4 v4 = *(const float4*)&sV[ss][vb];
            acc[0][0] += k4.x * v4.x; acc[0][1] += k4.x * v4.y; acc[0][2] += k4.x * v4.z; acc[0][3] += k4.x * v4.w;
            acc[1][0] += k4.y * v4.x; acc[1][1] += k4.y * v4.y; acc[1][2] += k4.y * v4.z; acc[1][3] += k4.y * v4.w;
            acc[2][0] += k4.z * v4.x; acc[2][1] += k4.z * v4.y; acc[2][2] += k4.z * v4.z; acc[2][3] += k4.z * v4.w;
            acc[3][0] += k4.w * v4.x; acc[3][1] += k4.w * v4.y; acc[3][2] += k4.w * v4.z; acc[3][3] += k4.w * v4.w;
        }
        if (g == 0 && t < 32) {
#pragma unroll
            for (int ss = 0; ss < 64; ss++) ksum += sK[ss][t];
        }
        __syncthreads();
    }

#pragma unroll
    for (int jd = 0; jd < 4; jd++)
#pragma unroll
        for (int jv = 0; jv < 4; jv++) red[g][t][jd * 4 + jv] = acc[jd][jv];
    __syncthreads();

    const size_t kvbase = (size_t)((n * H + h) * D) * D;
#pragma unroll
    for (int q = 0; q < 4; q++) {
        int o = tid * 4 + q;
        int d = o >> 5, v = o & 31;
        int tt = ((d >> 2) << 3) | (v >> 2);
        int jj = ((d & 3) << 2) | (v & 3);
        float val = red[0][tt][jj] + red[1][tt][jj] + red[2][tt][jj] + red[3][tt][jj];
        g_KVp[split][kvbase + (size_t)d * D + v] = val;
    }
    if (g == 0 && t < 32) g_Ksump[split][(size_t)(n * H + h) * D + t] = ksum;
}

// ---------------- KV partial reduction ----------------
__global__ void kv_reduce_kernel() {
    const int NKV = NB * H * D * D;
    const int NKS = NB * H * D;
    int i = blockIdx.x * blockDim.x + threadIdx.x;
    if (i < NKV) {
        float s = 0.f;
#pragma unroll
        for (int p = 0; p < KV_SPLIT; p++) s += g_KVp[p][i];
        g_KV[i] = s;
    } else if (i < NKV + NKS) {
        int j = i - NKV;
        float s = 0.f;
#pragma unroll
        for (int p = 0; p < KV_SPLIT; p++) s += g_Ksump[p][j];
        g_Ksum[j] = s;
    }
}

// ---------------- attention apply: O = (Qf @ KV) * Z * S ----------------
__global__ __launch_bounds__(256)
void attn_kernel(const float* __restrict__ Qf, float* __restrict__ O)
{
    const int bid  = blockIdx.x;
    const int n    = bid >> 12;
    const int h    = (bid >> 9) & 7;
    const int lgrp = bid & 511;

    __shared__ float sKV[32][32];
    __shared__ float sKs[32];

    const int tid = threadIdx.x;
    const float* kvp = g_KV + (size_t)((n * H + h) * D) * D;
    ((float4*)sKV)[tid] = ((const float4*)kvp)[tid];
    if (tid < 32) sKs[tid] = g_Ksum[(size_t)(n * H + h) * D + tid];
    __syncthreads();

    const int w = tid >> 5, lane = tid & 31;
    const int l = (lgrp << 3) | w;
    const size_t ro = ((size_t)n * L + l) * E + (size_t)h * D;

    float qf = Qf[ro + lane];
    float z = qf * sKs[lane];
#pragma unroll
    for (int o = 16; o; o >>= 1) z += __shfl_xor_sync(0xffffffffu, z, o);
    float zinv = (float)S / (z + EPS);

    float acc = 0.f;
#pragma unroll
    for (int d = 0; d < 32; d++)
        acc += __shfl_sync(0xffffffffu, qf, d) * sKV[d][lane];

    O[ro + lane] = acc * zinv;
}

// ---------------- launch ----------------
extern "C" void kernel_launch(void* const* d_in, const int* in_sizes, int n_in,
                              void* d_out, int out_size)
{
    const float* q   = (const float*)d_in[0];
    const float* k   = (const float*)d_in[1];
    const float* v   = (const float*)d_in[2];
    const void*  qmask = d_in[3];
    const void*  kmask = d_in[4];
    const float* Wq  = (const float*)d_in[5];
    const float* bq  = (const float*)d_in[6];
    const float* Wk  = (const float*)d_in[7];
    const float* bk  = (const float*)d_in[8];
    const float* Wv  = (const float*)d_in[9];
    const float* bv  = (const float*)d_in[10];
    const float* Wm  = (const float*)d_in[11];
    float* out = (float*)d_out;

    float* g_qm_p; cudaGetSymbolAddress((void**)&g_qm_p, g_qm);
    float* g_km_p; cudaGetSymbolAddress((void**)&g_km_p, g_km);
    float* g_Qf_p; cudaGetSymbolAddress((void**)&g_Qf_p, g_Qf);
    float* g_Kf_p; cudaGetSymbolAddress((void**)&g_Kf_p, g_Kf);
    float* g_Vm_p; cudaGetSymbolAddress((void**)&g_Vm_p, g_Vm);
    float* g_O_p;  cudaGetSymbolAddress((void**)&g_O_p,  g_O);

    // 1) mask dtype detect + convert
    detect_mask_kernel<<<1, 1>>>(qmask);
    convert_mask_kernel<<<(NL + 255) / 256, 256>>>(qmask, g_qm_p, NL);
    convert_mask_kernel<<<(NS + 255) / 256, 256>>>(kmask, g_km_p, NS);

    // 2) fused QKV projections (fp16 tensor cores, fp32 accumulate)
    dim3 ggrid(E / BN, NL / BM);
    gemm_f16<<<ggrid, 256>>>(q, Wq, bq, g_Qf_p, g_qm_p, 1.0f, 1);
    gemm_f16<<<ggrid, 256>>>(k, Wk, bk, g_Kf_p, g_km_p, 1.0f, 1);
    gemm_f16<<<ggrid, 256>>>(v, Wv, bv, g_Vm_p, g_km_p, 1.0f / (float)S, 2);

    // 3) KV aggregation (s-split) + reduction
    dim3 kvgrid(NB * H, KV_SPLIT);
    kv_agg_kernel<<<kvgrid, 256>>>(g_Kf_p, g_Vm_p);
    kv_reduce_kernel<<<(NB * H * D * D + NB * H * D + 255) / 256, 256>>>();

    // 4) attention apply
    attn_kernel<<<NB * H * (L / 8), 256>>>(g_Qf_p, g_O_p);

    // 5) merge projection (no bias)
    gemm_f16<<<ggrid, 256>>>(g_O_p, Wm, nullptr, out, nullptr, 1.0f, 0);
}

// round 12
// speedup vs baseline: 1.7609x; 1.0612x over previous
#include <cuda_runtime.h>
#include <cuda_fp16.h>
#include <math.h>
#include <stdint.h>

// Problem constants
constexpr int NB = 8;
constexpr int L  = 4096;
constexpr int S  = 4096;
constexpr int E  = 256;
constexpr int H  = 8;
constexpr int D  = 32;
constexpr int NL = NB * L;   // 32768
constexpr int NS = NB * S;   // 32768
constexpr float EPS = 1e-6f;
constexpr int KV_SPLIT = 8;

// ---------------- scratch (device globals; no allocation allowed) ----------------
__device__ float g_Qf[(size_t)NL * E];
__device__ float g_Kf[(size_t)NS * E];
__device__ float g_Vm[(size_t)NS * E];
__device__ float g_O [(size_t)NL * E];
__device__ float g_KV[(size_t)NB * H * D * D];
__device__ float g_Ksum[(size_t)NB * H * D];
__device__ float g_KVp[KV_SPLIT][(size_t)NB * H * D * D];
__device__ float g_Ksump[KV_SPLIT][(size_t)NB * H * D];
__device__ float g_qm[NL];
__device__ float g_km[NS];
__device__ int   g_mask_mode;

// ---------------- mask dtype detection + conversion ----------------
__global__ void detect_mask_kernel(const void* mask) {
    __shared__ int s_off1, s_3f;
    const int tid = threadIdx.x;   // 256 threads
    if (tid == 0) { s_off1 = 0; s_3f = 0; }
    __syncthreads();
    unsigned char c = ((const unsigned char*)mask)[tid];
    if ((tid & 3) == 1 && c == 1) atomicOr(&s_off1, 1);
    if (c == 0x3F)                atomicOr(&s_3f, 1);
    __syncthreads();
    if (tid == 0) g_mask_mode = s_off1 ? 0 : (s_3f ? 2 : 1);
}

__global__ void convert_mask_kernel(const void* __restrict__ m, float* __restrict__ out, int n) {
    int i = blockIdx.x * blockDim.x + threadIdx.x;
    if (i >= n) return;
    int mode = g_mask_mode;
    float v;
    if (mode == 0)      v = ((const unsigned char*)m)[i] ? 1.f : 0.f;
    else if (mode == 1) v = ((const int*)m)[i]           ? 1.f : 0.f;
    else                v = (((const float*)m)[i] != 0.f) ? 1.f : 0.f;
    out[i] = v;
}

// ---------------- fp16 MMA helpers ----------------
__device__ __forceinline__ uint32_t smem_u32(const void* p) {
    uint32_t r;
    asm("{ .reg .u64 t; cvta.to.shared.u64 t, %1; cvt.u32.u64 %0, t; }" : "=r"(r) : "l"(p));
    return r;
}

__device__ __forceinline__ uint32_t pack_h2(float x, float y) {
    __half2 h = __floats2half2_rn(x, y);
    return *(uint32_t*)&h;
}

__device__ __forceinline__ void ldmx4(uint32_t (&r)[4], uint32_t addr) {
    asm volatile("ldmatrix.sync.aligned.m8n8.x4.shared.b16 {%0,%1,%2,%3}, [%4];"
                 : "=r"(r[0]), "=r"(r[1]), "=r"(r[2]), "=r"(r[3]) : "r"(addr));
}

__device__ __forceinline__ void mma_f16(float (&d)[4], const uint32_t (&a)[4],
                                        uint32_t b0, uint32_t b1) {
    asm volatile(
        "mma.sync.aligned.m16n8k16.row.col.f32.f16.f16.f32 "
        "{%0,%1,%2,%3}, {%4,%5,%6,%7}, {%8,%9}, {%0,%1,%2,%3};"
        : "+f"(d[0]), "+f"(d[1]), "+f"(d[2]), "+f"(d[3])
        : "r"(a[0]), "r"(a[1]), "r"(a[2]), "r"(a[3]), "r"(b0), "r"(b1));
}

// ---------------- fp16 tensor-core GEMM: C = A @ W^T (+bias) with epilogue ----------------
// A: [M, E] row-major fp32, W: [E, E] row-major fp32 (C[m,n] = sum_k A[m,k]*W[n,k])
// mode 0: plain    mode 1: (elu(x)+1) * rowmask    mode 2: x * rowmask * scale
//
// Block tile 128x128, BK=32 (fp16 in smem), DOUBLE-BUFFERED: one __syncthreads per
// k-iteration; STS of tile c+1 overlaps MMAs of tile c.
// SMEM layout per matrix per buffer: 128 rows x 64B; 16B chunk c16 of row r at
// r*64 + (c16 ^ ((r>>1)&3))*16  (conflict-free STS.128 + ldmatrix).
#define BM 128
#define BN 128
#define BK 32
#define BUFB 8192   // bytes per buffer per matrix

__global__ __launch_bounds__(256, 2)
void gemm_f16(const float* __restrict__ A,
              const float* __restrict__ W,
              const float* __restrict__ bias,
              float* __restrict__ C,
              const float* __restrict__ rowmask,
              float scale, int mode)
{
    __shared__ __align__(16) unsigned char smA[2 * BUFB];  // 16KB
    __shared__ __align__(16) unsigned char smB[2 * BUFB];  // 16KB

    const int tid  = threadIdx.x;
    const int wid  = tid >> 5;
    const int lane = tid & 31;
    const int m0   = blockIdx.y * BM;
    const int n0   = blockIdx.x * BN;
    const int wm   = (wid & 1) * 64;   // warp M offset (2 warps in M)
    const int wn   = (wid >> 1) * 32;  // warp N offset (4 warps in N)
    const int g    = lane >> 2;
    const int tg   = lane & 3;

    const uint32_t sA = smem_u32(smA);
    const uint32_t sB = smem_u32(smB);

    // ---- fill indices (constant across k-tiles) ----
    int   fr[2], fc[2];
    uint32_t foff[2];
#pragma unroll
    for (int p = 0; p < 2; p++) {
        int idx = p * 256 + tid;
        fr[p] = idx >> 2;
        fc[p] = idx & 3;
        foff[p] = (uint32_t)(fr[p] * 64 + ((fc[p] ^ ((fr[p] >> 1) & 3)) << 4));
    }

    // ---- ldmatrix addresses (constant across k-tiles; buffer offset added per iter) ----
    uint32_t adA[4][2], adB[2][2];
#pragma unroll
    for (int i = 0; i < 4; i++) {
        int r = wm + i * 16 + ((lane >> 3) & 1) * 8 + (lane & 7);
#pragma unroll
        for (int s = 0; s < 2; s++) {
            int kc = 2 * s + (lane >> 4);
            adA[i][s] = sA + (uint32_t)(r * 64 + ((kc ^ ((r >> 1) & 3)) << 4));
        }
    }
#pragma unroll
    for (int jp = 0; jp < 2; jp++) {
        int r = wn + (2 * jp + ((lane >> 3) >> 1)) * 8 + (lane & 7);
#pragma unroll
        for (int s = 0; s < 2; s++) {
            int kc = 2 * s + ((lane >> 3) & 1);
            adB[jp][s] = sB + (uint32_t)(r * 64 + ((kc ^ ((r >> 1) & 3)) << 4));
        }
    }

    float acc[4][4][4];
#pragma unroll
    for (int i = 0; i < 4; i++)
#pragma unroll
        for (int j = 0; j < 4; j++)
#pragma unroll
            for (int r = 0; r < 4; r++) acc[i][j][r] = 0.f;

    // ---- prologue: load+convert tile 0 into staged regs ----
    uint4 stA[2], stB[2];
#pragma unroll
    for (int p = 0; p < 2; p++) {
        const float* pa = &A[(size_t)(m0 + fr[p]) * E + fc[p] * 8];
        float4 f0 = *(const float4*)pa;
        float4 f1 = *(const float4*)(pa + 4);
        stA[p] = make_uint4(pack_h2(f0.x, f0.y), pack_h2(f0.z, f0.w),
                            pack_h2(f1.x, f1.y), pack_h2(f1.z, f1.w));
        const float* pb = &W[(size_t)(n0 + fr[p]) * E + fc[p] * 8];
        float4 g0 = *(const float4*)pb;
        float4 g1 = *(const float4*)(pb + 4);
        stB[p] = make_uint4(pack_h2(g0.x, g0.y), pack_h2(g0.z, g0.w),
                            pack_h2(g1.x, g1.y), pack_h2(g1.z, g1.w));
    }

#pragma unroll
    for (int c = 0; c < E / BK; c++) {
        const uint32_t boff = (uint32_t)(c & 1) * BUFB;
        // ---- commit staged tile to buffer c&1 ----
#pragma unroll
        for (int p = 0; p < 2; p++) {
            *(uint4*)(smA + boff + foff[p]) = stA[p];
            *(uint4*)(smB + boff + foff[p]) = stB[p];
        }
        __syncthreads();   // single barrier per iteration

        // ---- prefetch next tile (LDG + cvt) while MMAs run ----
        if (c + 1 < E / BK) {
            const int k1 = (c + 1) * BK;
#pragma unroll
            for (int p = 0; p < 2; p++) {
                const float* pa = &A[(size_t)(m0 + fr[p]) * E + k1 + fc[p] * 8];
                float4 f0 = *(const float4*)pa;
                float4 f1 = *(const float4*)(pa + 4);
                stA[p] = make_uint4(pack_h2(f0.x, f0.y), pack_h2(f0.z, f0.w),
                                    pack_h2(f1.x, f1.y), pack_h2(f1.z, f1.w));
                const float* pb = &W[(size_t)(n0 + fr[p]) * E + k1 + fc[p] * 8];
                float4 g0 = *(const float4*)pb;
                float4 g1 = *(const float4*)(pb + 4);
                stB[p] = make_uint4(pack_h2(g0.x, g0.y), pack_h2(g0.z, g0.w),
                                    pack_h2(g1.x, g1.y), pack_h2(g1.z, g1.w));
            }
        }

        // ---- 2 k16-steps: 6 ldmatrix.x4 + 16 MMA per step per warp ----
#pragma unroll
        for (int s = 0; s < 2; s++) {
            uint32_t a[4][4];
#pragma unroll
            for (int i = 0; i < 4; i++) ldmx4(a[i], adA[i][s] + boff);
            uint32_t bb[2][4];
#pragma unroll
            for (int jp = 0; jp < 2; jp++) ldmx4(bb[jp], adB[jp][s] + boff);
#pragma unroll
            for (int i = 0; i < 4; i++) {
#pragma unroll
                for (int j = 0; j < 4; j++) {
                    const int jp = j >> 1, hi = j & 1;
                    mma_f16(acc[i][j], a[i], bb[jp][hi * 2], bb[jp][hi * 2 + 1]);
                }
            }
        }
        // no second barrier: next iteration writes the OTHER buffer
    }

    // ---- epilogue ----
#pragma unroll
    for (int i = 0; i < 4; i++) {
        const int r0 = m0 + wm + i * 16 + g;
        const int r1 = r0 + 8;
        float rm0 = 0.f, rm1 = 0.f;
        if (mode != 0) { rm0 = rowmask[r0]; rm1 = rowmask[r1]; }
#pragma unroll
        for (int j = 0; j < 4; j++) {
            const int col = n0 + wn + j * 8 + 2 * tg;
            float b0 = 0.f, b1 = 0.f;
            if (bias) { b0 = bias[col]; b1 = bias[col + 1]; }
            float v0 = acc[i][j][0] + b0;
            float v1 = acc[i][j][1] + b1;
            float v2 = acc[i][j][2] + b0;
            float v3 = acc[i][j][3] + b1;
            if (mode == 1) {
                v0 = ((v0 > 0.f) ? (v0 + 1.f) : expf(v0)) * rm0;
                v1 = ((v1 > 0.f) ? (v1 + 1.f) : expf(v1)) * rm0;
                v2 = ((v2 > 0.f) ? (v2 + 1.f) : expf(v2)) * rm1;
                v3 = ((v3 > 0.f) ? (v3 + 1.f) : expf(v3)) * rm1;
            } else if (mode == 2) {
                v0 *= rm0 * scale; v1 *= rm0 * scale;
                v2 *= rm1 * scale; v3 *= rm1 * scale;
            }
            *(float2*)&C[(size_t)r0 * E + col] = make_float2(v0, v1);
            *(float2*)&C[(size_t)r1 * E + col] = make_float2(v2, v3);
        }
    }
}

// ---------------- KV aggregation (s-split): partial KV[n,h,d,v], Ksum[n,h,d] ----------------
__global__ __launch_bounds__(256)
void kv_agg_kernel(const float* __restrict__ Kf, const float* __restrict__ Vm)
{
    const int n = blockIdx.x >> 3;
    const int h = blockIdx.x & 7;
    const int split = blockIdx.y;
    const int sbeg = split * (S / KV_SPLIT);
    const int send = sbeg + (S / KV_SPLIT);

    __shared__ float sK[64][40];
    __shared__ float sV[64][40];
    __shared__ float red[4][64][16];

    const int tid = threadIdx.x;
    const int g = tid >> 6;
    const int t = tid & 63;
    const int db = (t >> 3) << 2;
    const int vb = (t & 7) << 2;

    const int lr = tid >> 3;
    const int lc = (tid & 7) << 2;

    float acc[4][4];
#pragma unroll
    for (int i = 0; i < 4; i++)
#pragma unroll
        for (int j = 0; j < 4; j++) acc[i][j] = 0.f;
    float ksum = 0.f;

    const size_t base = (size_t)n * S * E + (size_t)h * D;

    for (int s0 = sbeg; s0 < send; s0 += 64) {
#pragma unroll
        for (int p = 0; p < 2; p++) {
            int r = lr + p * 32;
            size_t off = base + (size_t)(s0 + r) * E + lc;
            *(float4*)&sK[r][lc] = *(const float4*)&Kf[off];
            *(float4*)&sV[r][lc] = *(const float4*)&Vm[off];
        }
        __syncthreads();

        for (int ss = g; ss < 64; ss += 4) {
            float4 k4 = *(const float4*)&sK[ss][db];
            float4 v4 = *(const float4*)&sV[ss][vb];
            acc[0][0] += k4.x * v4.x; acc[0][1] += k4.x * v4.y; acc[0][2] += k4.x * v4.z; acc[0][3] += k4.x * v4.w;
            acc[1][0] += k4.y * v4.x; acc[1][1] += k4.y * v4.y; acc[1][2] += k4.y * v4.z; acc[1][3] += k4.y * v4.w;
            acc[2][0] += k4.z * v4.x; acc[2][1] += k4.z * v4.y; acc[2][2] += k4.z * v4.z; acc[2][3] += k4.z * v4.w;
            acc[3][0] += k4.w * v4.x; acc[3][1] += k4.w * v4.y; acc[3][2] += k4.w * v4.z; acc[3][3] += k4.w * v4.w;
        }
        if (g == 0 && t < 32) {
#pragma unroll
            for (int ss = 0; ss < 64; ss++) ksum += sK[ss][t];
        }
        __syncthreads();
    }

#pragma unroll
    for (int jd = 0; jd < 4; jd++)
#pragma unroll
        for (int jv = 0; jv < 4; jv++) red[g][t][jd * 4 + jv] = acc[jd][jv];
    __syncthreads();

    const size_t kvbase = (size_t)((n * H + h) * D) * D;
#pragma unroll
    for (int q = 0; q < 4; q++) {
        int o = tid * 4 + q;
        int d = o >> 5, v = o & 31;
        int tt = ((d >> 2) << 3) | (v >> 2);
        int jj = ((d & 3) << 2) | (v & 3);
        float val = red[0][tt][jj] + red[1][tt][jj] + red[2][tt][jj] + red[3][tt][jj];
        g_KVp[split][kvbase + (size_t)d * D + v] = val;
    }
    if (g == 0 && t < 32) g_Ksump[split][(size_t)(n * H + h) * D + t] = ksum;
}

// ---------------- KV partial reduction ----------------
__global__ void kv_reduce_kernel() {
    const int NKV = NB * H * D * D;
    const int NKS = NB * H * D;
    int i = blockIdx.x * blockDim.x + threadIdx.x;
    if (i < NKV) {
        float s = 0.f;
#pragma unroll
        for (int p = 0; p < KV_SPLIT; p++) s += g_KVp[p][i];
        g_KV[i] = s;
    } else if (i < NKV + NKS) {
        int j = i - NKV;
        float s = 0.f;
#pragma unroll
        for (int p = 0; p < KV_SPLIT; p++) s += g_Ksump[p][j];
        g_Ksum[j] = s;
    }
}

// ---------------- attention apply: O = (Qf @ KV) * Z * S ----------------
__global__ __launch_bounds__(256)
void attn_kernel(const float* __restrict__ Qf, float* __restrict__ O)
{
    const int bid  = blockIdx.x;
    const int n    = bid >> 12;
    const int h    = (bid >> 9) & 7;
    const int lgrp = bid & 511;

    __shared__ float sKV[32][32];
    __shared__ float sKs[32];

    const int tid = threadIdx.x;
    const float* kvp = g_KV + (size_t)((n * H + h) * D) * D;
    ((float4*)sKV)[tid] = ((const float4*)kvp)[tid];
    if (tid < 32) sKs[tid] = g_Ksum[(size_t)(n * H + h) * D + tid];
    __syncthreads();

    const int w = tid >> 5, lane = tid & 31;
    const int l = (lgrp << 3) | w;
    const size_t ro = ((size_t)n * L + l) * E + (size_t)h * D;

    float qf = Qf[ro + lane];
    float z = qf * sKs[lane];
#pragma unroll
    for (int o = 16; o; o >>= 1) z += __shfl_xor_sync(0xffffffffu, z, o);
    float zinv = (float)S / (z + EPS);

    float acc = 0.f;
#pragma unroll
    for (int d = 0; d < 32; d++)
        acc += __shfl_sync(0xffffffffu, qf, d) * sKV[d][lane];

    O[ro + lane] = acc * zinv;
}

// ---------------- launch ----------------
extern "C" void kernel_launch(void* const* d_in, const int* in_sizes, int n_in,
                              void* d_out, int out_size)
{
    const float* q   = (const float*)d_in[0];
    const float* k   = (const float*)d_in[1];
    const float* v   = (const float*)d_in[2];
    const void*  qmask = d_in[3];
    const void*  kmask = d_in[4];
    const float* Wq  = (const float*)d_in[5];
    const float* bq  = (const float*)d_in[6];
    const float* Wk  = (const float*)d_in[7];
    const float* bk  = (const float*)d_in[8];
    const float* Wv  = (const float*)d_in[9];
    const float* bv  = (const float*)d_in[10];
    const float* Wm  = (const float*)d_in[11];
    float* out = (float*)d_out;

    float* g_qm_p; cudaGetSymbolAddress((void**)&g_qm_p, g_qm);
    float* g_km_p; cudaGetSymbolAddress((void**)&g_km_p, g_km);
    float* g_Qf_p; cudaGetSymbolAddress((void**)&g_Qf_p, g_Qf);
    float* g_Kf_p; cudaGetSymbolAddress((void**)&g_Kf_p, g_Kf);
    float* g_Vm_p; cudaGetSymbolAddress((void**)&g_Vm_p, g_Vm);
    float* g_O_p;  cudaGetSymbolAddress((void**)&g_O_p,  g_O);

    // 1) mask dtype detect + convert
    detect_mask_kernel<<<1, 256>>>(qmask);
    convert_mask_kernel<<<(NL + 255) / 256, 256>>>(qmask, g_qm_p, NL);
    convert_mask_kernel<<<(NS + 255) / 256, 256>>>(kmask, g_km_p, NS);

    // 2) fused QKV projections (fp16 tensor cores, fp32 accumulate)
    dim3 ggrid(E / BN, NL / BM);
    gemm_f16<<<ggrid, 256>>>(q, Wq, bq, g_Qf_p, g_qm_p, 1.0f, 1);
    gemm_f16<<<ggrid, 256>>>(k, Wk, bk, g_Kf_p, g_km_p, 1.0f, 1);
    gemm_f16<<<ggrid, 256>>>(v, Wv, bv, g_Vm_p, g_km_p, 1.0f / (float)S, 2);

    // 3) KV aggregation (s-split) + reduction
    dim3 kvgrid(NB * H, KV_SPLIT);
    kv_agg_kernel<<<kvgrid, 256>>>(g_Kf_p, g_Vm_p);
    kv_reduce_kernel<<<(NB * H * D * D + NB * H * D + 255) / 256, 256>>>();

    // 4) attention apply
    attn_kernel<<<NB * H * (L / 8), 256>>>(g_Qf_p, g_O_p);

    // 5) merge projection (no bias)
    gemm_f16<<<ggrid, 256>>>(g_O_p, Wm, nullptr, out, nullptr, 1.0f, 0);
}

// round 13
// speedup vs baseline: 1.8729x; 1.0636x over previous
#include <cuda_runtime.h>
#include <cuda_fp16.h>
#include <math.h>
#include <stdint.h>

// Problem constants
constexpr int NB = 8;
constexpr int L  = 4096;
constexpr int S  = 4096;
constexpr int E  = 256;
constexpr int H  = 8;
constexpr int D  = 32;
constexpr int NL = NB * L;   // 32768
constexpr int NS = NB * S;   // 32768
constexpr float EPS = 1e-6f;
constexpr int KV_SPLIT = 8;

// ---------------- scratch (device globals; no allocation allowed) ----------------
__device__ float  g_Qf[(size_t)NL * E];
__device__ float  g_Kf[(size_t)NS * E];
__device__ float  g_Vm[(size_t)NS * E];
__device__ __half g_Oh[(size_t)NL * E];      // attn output, fp16 (merge GEMM input)
__device__ __half g_qh[(size_t)NL * E];      // fp16 copies of inputs
__device__ __half g_kh[(size_t)NS * E];
__device__ __half g_vh[(size_t)NS * E];
__device__ __half g_Wh[4][(size_t)E * E];    // Wq, Wk, Wv, Wm in fp16
__device__ float  g_KV[(size_t)NB * H * D * D];
__device__ float  g_Ksum[(size_t)NB * H * D];
__device__ float  g_KVp[KV_SPLIT][(size_t)NB * H * D * D];
__device__ float  g_Ksump[KV_SPLIT][(size_t)NB * H * D];
__device__ float  g_qm[NL];
__device__ float  g_km[NS];
__device__ int    g_mask_mode;

// ---------------- helpers ----------------
__device__ __forceinline__ uint32_t smem_u32(const void* p) {
    uint32_t r;
    asm("{ .reg .u64 t; cvta.to.shared.u64 t, %1; cvt.u32.u64 %0, t; }" : "=r"(r) : "l"(p));
    return r;
}

__device__ __forceinline__ uint32_t pack_h2(float x, float y) {
    __half2 h = __floats2half2_rn(x, y);
    return *(uint32_t*)&h;
}

__device__ __forceinline__ void ldmx4(uint32_t (&r)[4], uint32_t addr) {
    asm volatile("ldmatrix.sync.aligned.m8n8.x4.shared.b16 {%0,%1,%2,%3}, [%4];"
                 : "=r"(r[0]), "=r"(r[1]), "=r"(r[2]), "=r"(r[3]) : "r"(addr));
}

__device__ __forceinline__ void mma_f16(float (&d)[4], const uint32_t (&a)[4],
                                        uint32_t b0, uint32_t b1) {
    asm volatile(
        "mma.sync.aligned.m16n8k16.row.col.f32.f16.f16.f32 "
        "{%0,%1,%2,%3}, {%4,%5,%6,%7}, {%8,%9}, {%0,%1,%2,%3};"
        : "+f"(d[0]), "+f"(d[1]), "+f"(d[2]), "+f"(d[3])
        : "r"(a[0]), "r"(a[1]), "r"(a[2]), "r"(a[3]), "r"(b0), "r"(b1));
}

__device__ __forceinline__ void cp_async16(uint32_t dst, const void* src) {
    asm volatile("cp.async.cg.shared.global [%0], [%1], 16;" :: "r"(dst), "l"(src) : "memory");
}
__device__ __forceinline__ void cp_commit() {
    asm volatile("cp.async.commit_group;" ::: "memory");
}
__device__ __forceinline__ void cp_wait2() {
    asm volatile("cp.async.wait_group 2;" ::: "memory");
}

// ---------------- mask dtype detection + conversion ----------------
__global__ void detect_mask_kernel(const void* mask) {
    __shared__ int s_off1, s_3f;
    const int tid = threadIdx.x;
    if (tid == 0) { s_off1 = 0; s_3f = 0; }
    __syncthreads();
    unsigned char c = ((const unsigned char*)mask)[tid];
    if ((tid & 3) == 1 && c == 1) atomicOr(&s_off1, 1);
    if (c == 0x3F)                atomicOr(&s_3f, 1);
    __syncthreads();
    if (tid == 0) g_mask_mode = s_off1 ? 0 : (s_3f ? 2 : 1);
}

__global__ void convert_mask_kernel(const void* __restrict__ m, float* __restrict__ out, int n) {
    int i = blockIdx.x * blockDim.x + threadIdx.x;
    if (i >= n) return;
    int mode = g_mask_mode;
    float v;
    if (mode == 0)      v = ((const unsigned char*)m)[i] ? 1.f : 0.f;
    else if (mode == 1) v = ((const int*)m)[i]           ? 1.f : 0.f;
    else                v = (((const float*)m)[i] != 0.f) ? 1.f : 0.f;
    out[i] = v;
}

// ---------------- fp32 -> fp16 conversion (inputs + weights) ----------------
__global__ void cvt_inputs_kernel(const float* __restrict__ a, const float* __restrict__ b,
                                  const float* __restrict__ c,
                                  __half* __restrict__ da, __half* __restrict__ db,
                                  __half* __restrict__ dc) {
    const int seg = blockIdx.y;
    const float* s = (seg == 0) ? a : (seg == 1) ? b : c;
    __half*      d = (seg == 0) ? da : (seg == 1) ? db : dc;
    size_t i = ((size_t)blockIdx.x * blockDim.x + threadIdx.x) * 8;
    float4 f0 = *(const float4*)&s[i];
    float4 f1 = *(const float4*)&s[i + 4];
    uint4 o = make_uint4(pack_h2(f0.x, f0.y), pack_h2(f0.z, f0.w),
                         pack_h2(f1.x, f1.y), pack_h2(f1.z, f1.w));
    *(uint4*)&d[i] = o;
}

__global__ void cvt_weights_kernel(const float* __restrict__ w0, const float* __restrict__ w1,
                                   const float* __restrict__ w2, const float* __restrict__ w3) {
    const int seg = blockIdx.y;
    const float* s = (seg == 0) ? w0 : (seg == 1) ? w1 : (seg == 2) ? w2 : w3;
    __half*      d = g_Wh[seg];
    size_t i = ((size_t)blockIdx.x * blockDim.x + threadIdx.x) * 8;
    float4 f0 = *(const float4*)&s[i];
    float4 f1 = *(const float4*)&s[i + 4];
    uint4 o = make_uint4(pack_h2(f0.x, f0.y), pack_h2(f0.z, f0.w),
                         pack_h2(f1.x, f1.y), pack_h2(f1.z, f1.w));
    *(uint4*)&d[i] = o;
}

// ---------------- fp16 tensor-core GEMM: C = A @ W^T (+bias) with epilogue ----------------
// A: [M, E] row-major fp16, W: [E, E] row-major fp16 (C[m,n] = sum_k A[m,k]*W[n,k])
// mode 0: plain    mode 1: (elu(x)+1) * rowmask    mode 2: x * rowmask * scale
//
// Block tile 128x128, BK=32 fp16, 4-stage cp.async pipeline.
// SMEM layout per matrix per stage: 128 rows x 64B; 16B chunk c16 of row r at
// r*64 + (c16 ^ ((r>>1)&3))*16  (conflict-free cp.async STS + ldmatrix).
#define BM 128
#define BN 128
#define BK 32
#define BUFB 8192
#define NSTAGE 4
constexpr int GEMM_DSMEM = 2 * NSTAGE * BUFB;   // 64KB

__global__ __launch_bounds__(256, 2)
void gemm_f16(const __half* __restrict__ A,
              const __half* __restrict__ W,
              const float* __restrict__ bias,
              float* __restrict__ C,
              const float* __restrict__ rowmask,
              float scale, int mode)
{
    extern __shared__ __align__(16) unsigned char dynsm[];
    const uint32_t sA = smem_u32(dynsm);
    const uint32_t sB = sA + NSTAGE * BUFB;

    const int tid  = threadIdx.x;
    const int wid  = tid >> 5;
    const int lane = tid & 31;
    const int m0   = blockIdx.y * BM;
    const int n0   = blockIdx.x * BN;
    const int wm   = (wid & 1) * 64;
    const int wn   = (wid >> 1) * 32;
    const int g    = lane >> 2;
    const int tg   = lane & 3;

    // ---- fill indices (constant): thread covers 2 chunks per matrix per stage ----
    int fr[2], fc[2];
    uint32_t foff[2];
#pragma unroll
    for (int p = 0; p < 2; p++) {
        int idx = p * 256 + tid;
        fr[p] = idx >> 2;
        fc[p] = idx & 3;
        foff[p] = (uint32_t)(fr[p] * 64 + ((fc[p] ^ ((fr[p] >> 1) & 3)) << 4));
    }

    // ---- ldmatrix addresses (stage offset added per iter) ----
    uint32_t adA[4][2], adB[2][2];
#pragma unroll
    for (int i = 0; i < 4; i++) {
        int r = wm + i * 16 + ((lane >> 3) & 1) * 8 + (lane & 7);
#pragma unroll
        for (int s = 0; s < 2; s++) {
            int kc = 2 * s + (lane >> 4);
            adA[i][s] = sA + (uint32_t)(r * 64 + ((kc ^ ((r >> 1) & 3)) << 4));
        }
    }
#pragma unroll
    for (int jp = 0; jp < 2; jp++) {
        int r = wn + (2 * jp + ((lane >> 3) >> 1)) * 8 + (lane & 7);
#pragma unroll
        for (int s = 0; s < 2; s++) {
            int kc = 2 * s + ((lane >> 3) & 1);
            adB[jp][s] = sB + (uint32_t)(r * 64 + ((kc ^ ((r >> 1) & 3)) << 4));
        }
    }

    float acc[4][4][4];
#pragma unroll
    for (int i = 0; i < 4; i++)
#pragma unroll
        for (int j = 0; j < 4; j++)
#pragma unroll
            for (int r = 0; r < 4; r++) acc[i][j][r] = 0.f;

    // stage issue: stage s covers K range [s*BK, s*BK+BK)
    auto issue_stage = [&](int s) {
        const uint32_t so = (uint32_t)(s & 3) * BUFB;
#pragma unroll
        for (int p = 0; p < 2; p++) {
            const __half* srcA = A + (size_t)(m0 + fr[p]) * E + s * BK + fc[p] * 8;
            cp_async16(sA + so + foff[p], srcA);
            const __half* srcB = W + (size_t)(n0 + fr[p]) * E + s * BK + fc[p] * 8;
            cp_async16(sB + so + foff[p], srcB);
        }
    };

    // prologue: 3 stages in flight
    issue_stage(0); cp_commit();
    issue_stage(1); cp_commit();
    issue_stage(2); cp_commit();

    constexpr int NITER = E / BK;   // 8
#pragma unroll
    for (int c = 0; c < NITER; c++) {
        cp_wait2();            // oldest group (stage c) complete
        __syncthreads();       // all warps see stage c; all reads of buffer (c-1)&3 done
        if (c + 3 < NITER) issue_stage(c + 3);
        cp_commit();           // unconditional: keeps 3 groups pending through the tail

        const uint32_t boff = (uint32_t)(c & 3) * BUFB;
#pragma unroll
        for (int s = 0; s < 2; s++) {
            uint32_t a[4][4];
#pragma unroll
            for (int i = 0; i < 4; i++) ldmx4(a[i], adA[i][s] + boff);
            uint32_t bb[2][4];
#pragma unroll
            for (int jp = 0; jp < 2; jp++) ldmx4(bb[jp], adB[jp][s] + boff);
#pragma unroll
            for (int i = 0; i < 4; i++) {
#pragma unroll
                for (int j = 0; j < 4; j++) {
                    const int jp = j >> 1, hi = j & 1;
                    mma_f16(acc[i][j], a[i], bb[jp][hi * 2], bb[jp][hi * 2 + 1]);
                }
            }
        }
    }

    // ---- epilogue ----
#pragma unroll
    for (int i = 0; i < 4; i++) {
        const int r0 = m0 + wm + i * 16 + g;
        const int r1 = r0 + 8;
        float rm0 = 0.f, rm1 = 0.f;
        if (mode != 0) { rm0 = rowmask[r0]; rm1 = rowmask[r1]; }
#pragma unroll
        for (int j = 0; j < 4; j++) {
            const int col = n0 + wn + j * 8 + 2 * tg;
            float b0 = 0.f, b1 = 0.f;
            if (bias) { b0 = bias[col]; b1 = bias[col + 1]; }
            float v0 = acc[i][j][0] + b0;
            float v1 = acc[i][j][1] + b1;
            float v2 = acc[i][j][2] + b0;
            float v3 = acc[i][j][3] + b1;
            if (mode == 1) {
                v0 = ((v0 > 0.f) ? (v0 + 1.f) : expf(v0)) * rm0;
                v1 = ((v1 > 0.f) ? (v1 + 1.f) : expf(v1)) * rm0;
                v2 = ((v2 > 0.f) ? (v2 + 1.f) : expf(v2)) * rm1;
                v3 = ((v3 > 0.f) ? (v3 + 1.f) : expf(v3)) * rm1;
            } else if (mode == 2) {
                v0 *= rm0 * scale; v1 *= rm0 * scale;
                v2 *= rm1 * scale; v3 *= rm1 * scale;
            }
            *(float2*)&C[(size_t)r0 * E + col] = make_float2(v0, v1);
            *(float2*)&C[(size_t)r1 * E + col] = make_float2(v2, v3);
        }
    }
}

// ---------------- KV aggregation (s-split): partial KV[n,h,d,v], Ksum[n,h,d] ----------------
__global__ __launch_bounds__(256)
void kv_agg_kernel(const float* __restrict__ Kf, const float* __restrict__ Vm)
{
    const int n = blockIdx.x >> 3;
    const int h = blockIdx.x & 7;
    const int split = blockIdx.y;
    const int sbeg = split * (S / KV_SPLIT);
    const int send = sbeg + (S / KV_SPLIT);

    __shared__ float sK[64][40];
    __shared__ float sV[64][40];
    __shared__ float red[4][64][16];

    const int tid = threadIdx.x;
    const int g = tid >> 6;
    const int t = tid & 63;
    const int db = (t >> 3) << 2;
    const int vb = (t & 7) << 2;

    const int lr = tid >> 3;
    const int lc = (tid & 7) << 2;

    float acc[4][4];
#pragma unroll
    for (int i = 0; i < 4; i++)
#pragma unroll
        for (int j = 0; j < 4; j++) acc[i][j] = 0.f;
    float ksum = 0.f;

    const size_t base = (size_t)n * S * E + (size_t)h * D;

    for (int s0 = sbeg; s0 < send; s0 += 64) {
#pragma unroll
        for (int p = 0; p < 2; p++) {
            int r = lr + p * 32;
            size_t off = base + (size_t)(s0 + r) * E + lc;
            *(float4*)&sK[r][lc] = *(const float4*)&Kf[off];
            *(float4*)&sV[r][lc] = *(const float4*)&Vm[off];
        }
        __syncthreads();

        for (int ss = g; ss < 64; ss += 4) {
            float4 k4 = *(const float4*)&sK[ss][db];
            float4 v4 = *(const float4*)&sV[ss][vb];
            acc[0][0] += k4.x * v4.x; acc[0][1] += k4.x * v4.y; acc[0][2] += k4.x * v4.z; acc[0][3] += k4.x * v4.w;
            acc[1][0] += k4.y * v4.x; acc[1][1] += k4.y * v4.y; acc[1][2] += k4.y * v4.z; acc[1][3] += k4.y * v4.w;
            acc[2][0] += k4.z * v4.x; acc[2][1] += k4.z * v4.y; acc[2][2] += k4.z * v4.z; acc[2][3] += k4.z * v4.w;
            acc[3][0] += k4.w * v4.x; acc[3][1] += k4.w * v4.y; acc[3][2] += k4.w * v4.z; acc[3][3] += k4.w * v4.w;
        }
        if (g == 0 && t < 32) {
#pragma unroll
            for (int ss = 0; ss < 64; ss++) ksum += sK[ss][t];
        }
        __syncthreads();
    }

#pragma unroll
    for (int jd = 0; jd < 4; jd++)
#pragma unroll
        for (int jv = 0; jv < 4; jv++) red[g][t][jd * 4 + jv] = acc[jd][jv];
    __syncthreads();

    const size_t kvbase = (size_t)((n * H + h) * D) * D;
#pragma unroll
    for (int q = 0; q < 4; q++) {
        int o = tid * 4 + q;
        int d = o >> 5, v = o & 31;
        int tt = ((d >> 2) << 3) | (v >> 2);
        int jj = ((d & 3) << 2) | (v & 3);
        float val = red[0][tt][jj] + red[1][tt][jj] + red[2][tt][jj] + red[3][tt][jj];
        g_KVp[split][kvbase + (size_t)d * D + v] = val;
    }
    if (g == 0 && t < 32) g_Ksump[split][(size_t)(n * H + h) * D + t] = ksum;
}

// ---------------- KV partial reduction ----------------
__global__ void kv_reduce_kernel() {
    const int NKV = NB * H * D * D;
    const int NKS = NB * H * D;
    int i = blockIdx.x * blockDim.x + threadIdx.x;
    if (i < NKV) {
        float s = 0.f;
#pragma unroll
        for (int p = 0; p < KV_SPLIT; p++) s += g_KVp[p][i];
        g_KV[i] = s;
    } else if (i < NKV + NKS) {
        int j = i - NKV;
        float s = 0.f;
#pragma unroll
        for (int p = 0; p < KV_SPLIT; p++) s += g_Ksump[p][j];
        g_Ksum[j] = s;
    }
}

// ---------------- attention apply: Oh = fp16( (Qf @ KV) * Z * S ) ----------------
__global__ __launch_bounds__(256)
void attn_kernel(const float* __restrict__ Qf, __half* __restrict__ O)
{
    const int bid  = blockIdx.x;
    const int n    = bid >> 12;
    const int h    = (bid >> 9) & 7;
    const int lgrp = bid & 511;

    __shared__ float sKV[32][32];
    __shared__ float sKs[32];

    const int tid = threadIdx.x;
    const float* kvp = g_KV + (size_t)((n * H + h) * D) * D;
    ((float4*)sKV)[tid] = ((const float4*)kvp)[tid];
    if (tid < 32) sKs[tid] = g_Ksum[(size_t)(n * H + h) * D + tid];
    __syncthreads();

    const int w = tid >> 5, lane = tid & 31;
    const int l = (lgrp << 3) | w;
    const size_t ro = ((size_t)n * L + l) * E + (size_t)h * D;

    float qf = Qf[ro + lane];
    float z = qf * sKs[lane];
#pragma unroll
    for (int o = 16; o; o >>= 1) z += __shfl_xor_sync(0xffffffffu, z, o);
    float zinv = (float)S / (z + EPS);

    float acc = 0.f;
#pragma unroll
    for (int d = 0; d < 32; d++)
        acc += __shfl_sync(0xffffffffu, qf, d) * sKV[d][lane];

    O[ro + lane] = __float2half(acc * zinv);
}

// ---------------- launch ----------------
extern "C" void kernel_launch(void* const* d_in, const int* in_sizes, int n_in,
                              void* d_out, int out_size)
{
    const float* q   = (const float*)d_in[0];
    const float* k   = (const float*)d_in[1];
    const float* v   = (const float*)d_in[2];
    const void*  qmask = d_in[3];
    const void*  kmask = d_in[4];
    const float* Wq  = (const float*)d_in[5];
    const float* bq  = (const float*)d_in[6];
    const float* Wk  = (const float*)d_in[7];
    const float* bk  = (const float*)d_in[8];
    const float* Wv  = (const float*)d_in[9];
    const float* bv  = (const float*)d_in[10];
    const float* Wm  = (const float*)d_in[11];
    float* out = (float*)d_out;

    float*  g_qm_p; cudaGetSymbolAddress((void**)&g_qm_p, g_qm);
    float*  g_km_p; cudaGetSymbolAddress((void**)&g_km_p, g_km);
    float*  g_Qf_p; cudaGetSymbolAddress((void**)&g_Qf_p, g_Qf);
    float*  g_Kf_p; cudaGetSymbolAddress((void**)&g_Kf_p, g_Kf);
    float*  g_Vm_p; cudaGetSymbolAddress((void**)&g_Vm_p, g_Vm);
    __half* g_Oh_p; cudaGetSymbolAddress((void**)&g_Oh_p, g_Oh);
    __half* g_qh_p; cudaGetSymbolAddress((void**)&g_qh_p, g_qh);
    __half* g_kh_p; cudaGetSymbolAddress((void**)&g_kh_p, g_kh);
    __half* g_vh_p; cudaGetSymbolAddress((void**)&g_vh_p, g_vh);
    __half* g_Wh_p; cudaGetSymbolAddress((void**)&g_Wh_p, g_Wh);

    static bool attr_set = false;
    if (!attr_set) {
        cudaFuncSetAttribute(gemm_f16, cudaFuncAttributeMaxDynamicSharedMemorySize, GEMM_DSMEM);
        attr_set = true;
    }

    // 1) mask detect/convert + fp16 conversions (independent; front of graph)
    detect_mask_kernel<<<1, 256>>>(qmask);
    convert_mask_kernel<<<(NL + 255) / 256, 256>>>(qmask, g_qm_p, NL);
    convert_mask_kernel<<<(NS + 255) / 256, 256>>>(kmask, g_km_p, NS);
    dim3 cgrid((NL * E / 8 + 255) / 256, 3);
    cvt_inputs_kernel<<<cgrid, 256>>>(q, k, v, g_qh_p, g_kh_p, g_vh_p);
    dim3 wgrid((E * E / 8 + 255) / 256, 4);
    cvt_weights_kernel<<<wgrid, 256>>>(Wq, Wk, Wv, Wm);

    // 2) fused QKV projections (fp16 tensor cores + cp.async pipeline)
    dim3 ggrid(E / BN, NL / BM);
    gemm_f16<<<ggrid, 256, GEMM_DSMEM>>>(g_qh_p, g_Wh_p + 0 * (size_t)E * E, bq, g_Qf_p, g_qm_p, 1.0f, 1);
    gemm_f16<<<ggrid, 256, GEMM_DSMEM>>>(g_kh_p, g_Wh_p + 1 * (size_t)E * E, bk, g_Kf_p, g_km_p, 1.0f, 1);
    gemm_f16<<<ggrid, 256, GEMM_DSMEM>>>(g_vh_p, g_Wh_p + 2 * (size_t)E * E, bv, g_Vm_p, g_km_p, 1.0f / (float)S, 2);

    // 3) KV aggregation (s-split) + reduction
    dim3 kvgrid(NB * H, KV_SPLIT);
    kv_agg_kernel<<<kvgrid, 256>>>(g_Kf_p, g_Vm_p);
    kv_reduce_kernel<<<(NB * H * D * D + NB * H * D + 255) / 256, 256>>>();

    // 4) attention apply (fp16 output)
    attn_kernel<<<NB * H * (L / 8), 256>>>(g_Qf_p, g_Oh_p);

    // 5) merge projection (no bias)
    gemm_f16<<<ggrid, 256, GEMM_DSMEM>>>(g_Oh_p, g_Wh_p + 3 * (size_t)E * E, nullptr, out, nullptr, 1.0f, 0);
}